// round 1
// baseline (speedup 1.0000x reference)
#include <cuda_runtime.h>
#include <cuda_bf16.h>
#include <math.h>

#define NN 50000
#define EE 600000
#define DD 128
#define NF (NN*DD)   // 6,400,000 floats per feature matrix

// ---------------------------------------------------------------------------
// Scratch layout (single static device array; zero-region is the front part)
//  [0,      NF)  AGG1B   (zeroed)
//  [NF,    2NF)  AGG1A   (zeroed)
//  [2NF,   3NF)  AGG2B   (zeroed)
//  [3NF,   4NF)  AGG2A   (zeroed)
//  [4NF,   5NF)  HB
//  [5NF,   6NF)  HA
//  [6NF,   7NF)  H2A
//  [7NF,   8NF)  H2B
//  [8NF,   9NF)  HMLP
//  [9NF, 9NF+200000)        DEG: rs_src_r0[N], rs_dst_r0[N], rs_src_r1[N], rs_dst_r1[N]  (zeroed)
//  [9NF+200000, +256)       STATS: colsum[128], colsumsq[128]                            (zeroed)
//  [9NF+200256, +256)       BN: scale[128], shift[128]
// ---------------------------------------------------------------------------
#define OFF_AGG1B 0ULL
#define OFF_AGG1A (1ULL*NF)
#define OFF_AGG2B (2ULL*NF)
#define OFF_AGG2A (3ULL*NF)
#define OFF_HB    (4ULL*NF)
#define OFF_HA    (5ULL*NF)
#define OFF_H2A   (6ULL*NF)
#define OFF_H2B   (7ULL*NF)
#define OFF_HMLP  (8ULL*NF)
#define OFF_DEG   (9ULL*NF)
#define OFF_STATS (9ULL*NF + 200000ULL)
#define OFF_BN    (9ULL*NF + 200256ULL)
#define SCRATCH_FLOATS (9ULL*NF + 200512ULL)

__device__ __align__(256) float g_s[SCRATCH_FLOATS];

// ---------------------------------------------------------------------------
// zero a float4-aligned region
__global__ void k_zero(float* __restrict__ p, long n4) {
    long i = (long)blockIdx.x * blockDim.x + threadIdx.x;
    if (i < n4) ((float4*)p)[i] = make_float4(0.f, 0.f, 0.f, 0.f);
}

// degree counts for both relations (float counts via atomicAdd)
__global__ void k_degree(const int* __restrict__ s0, const int* __restrict__ d0,
                         const int* __restrict__ s1, const int* __restrict__ d1,
                         float* __restrict__ deg) {
    int i = blockIdx.x * blockDim.x + threadIdx.x;
    if (i < EE) {
        atomicAdd(&deg[0 * NN + s0[i]], 1.f);
        atomicAdd(&deg[1 * NN + d0[i]], 1.f);
        atomicAdd(&deg[2 * NN + s1[i]], 1.f);
        atomicAdd(&deg[3 * NN + d1[i]], 1.f);
    }
}

__global__ void k_rsqrt(float* __restrict__ deg) {
    int i = blockIdx.x * blockDim.x + threadIdx.x;
    if (i < 4 * NN) deg[i] = rsqrtf(fmaxf(deg[i], 1.f));
}

// ---------------------------------------------------------------------------
// scatter: agg[dst] += x[src] * rs_src[src]   (one warp per edge, float4 lanes)
__global__ void __launch_bounds__(256) k_scatter(
    const float* __restrict__ x, const int* __restrict__ src,
    const int* __restrict__ dst, const float* __restrict__ rs,
    float* __restrict__ agg) {
    int g = blockIdx.x * blockDim.x + threadIdx.x;
    int e = g >> 5;
    int lane = g & 31;
    if (e >= EE) return;
    int s = __ldg(src + e);
    int d = __ldg(dst + e);
    float r = __ldg(rs + s);
    float4 v = __ldg((const float4*)(x + (long)s * DD) + lane);
    v.x *= r; v.y *= r; v.z *= r; v.w *= r;
    float* p = agg + (long)d * DD + lane * 4;
    asm volatile("red.global.add.v4.f32 [%0], {%1,%2,%3,%4};"
                 :: "l"(p), "f"(v.x), "f"(v.y), "f"(v.z), "f"(v.w)
                 : "memory");
}

// ---------------------------------------------------------------------------
// out[r,:] = act( (X[r,:] * rs[r]) @ W + b ),  X: [N,128], W: [128,128]
// block = 256 threads, 64 rows x 128 cols per block; W + A tile in smem (96KB)
__global__ void __launch_bounds__(256) k_gemm128(
    const float* __restrict__ X, const float* __restrict__ rs,
    const float* __restrict__ W, const float* __restrict__ b,
    float* __restrict__ out, int doRelu) {
    extern __shared__ float sm[];
    float* sW = sm;                 // 128*128
    float* sA = sm + 128 * 128;     // 64*128
    int tid = threadIdx.x;
    int r0 = blockIdx.x * 64;

    for (int i = tid; i < 128 * 128 / 4; i += 256)
        ((float4*)sW)[i] = ((const float4*)W)[i];
    for (int i = tid; i < 64 * 128 / 4; i += 256) {
        int row = i >> 5;
        int gr = r0 + row;
        float4 v = make_float4(0.f, 0.f, 0.f, 0.f);
        if (gr < NN) {
            v = ((const float4*)(X + (long)gr * DD))[i & 31];
            float r = rs[gr];
            v.x *= r; v.y *= r; v.z *= r; v.w *= r;
        }
        ((float4*)sA)[i] = v;
    }
    __syncthreads();

    int tx = tid & 31, ty = tid >> 5;
    float4 bb = ((const float4*)b)[tx];
    float acc[8][4];
#pragma unroll
    for (int i = 0; i < 8; i++) {
        acc[i][0] = bb.x; acc[i][1] = bb.y; acc[i][2] = bb.z; acc[i][3] = bb.w;
    }

#pragma unroll 8
    for (int k = 0; k < 128; k++) {
        float4 w = ((float4*)(sW + k * 128))[tx];
#pragma unroll
        for (int i = 0; i < 8; i++) {
            float a = sA[(ty * 8 + i) * 128 + k];
            acc[i][0] += a * w.x; acc[i][1] += a * w.y;
            acc[i][2] += a * w.z; acc[i][3] += a * w.w;
        }
    }

#pragma unroll
    for (int i = 0; i < 8; i++) {
        int gr = r0 + ty * 8 + i;
        if (gr < NN) {
            float4 o = make_float4(acc[i][0], acc[i][1], acc[i][2], acc[i][3]);
            if (doRelu) {
                o.x = fmaxf(o.x, 0.f); o.y = fmaxf(o.y, 0.f);
                o.z = fmaxf(o.z, 0.f); o.w = fmaxf(o.w, 0.f);
            }
            ((float4*)(out + (long)gr * DD))[tx] = o;
        }
    }
}

// ---------------------------------------------------------------------------
// MLP layer 1 with implicit concat: out = XA @ Wm1[0:128,:] + XB @ Wm1[128:256,:]
// also accumulates per-column sum / sumsq into stat[] (for BN over 50000 rows)
__global__ void __launch_bounds__(256) k_mlp1(
    const float* __restrict__ XA, const float* __restrict__ XB,
    const float* __restrict__ Wm1, float* __restrict__ out,
    float* __restrict__ stat) {
    extern __shared__ float sm[];
    float* sW = sm;
    float* sA = sm + 128 * 128;
    int tid = threadIdx.x;
    int r0 = blockIdx.x * 64;
    int tx = tid & 31, ty = tid >> 5;

    float acc[8][4];
#pragma unroll
    for (int i = 0; i < 8; i++)
        acc[i][0] = acc[i][1] = acc[i][2] = acc[i][3] = 0.f;

    for (int phase = 0; phase < 2; phase++) {
        const float* X = phase ? XB : XA;
        const float* Wp = Wm1 + phase * 128 * 128;
        for (int i = tid; i < 128 * 128 / 4; i += 256)
            ((float4*)sW)[i] = ((const float4*)Wp)[i];
        for (int i = tid; i < 64 * 128 / 4; i += 256) {
            int row = i >> 5;
            int gr = r0 + row;
            float4 v = make_float4(0.f, 0.f, 0.f, 0.f);
            if (gr < NN) v = ((const float4*)(X + (long)gr * DD))[i & 31];
            ((float4*)sA)[i] = v;
        }
        __syncthreads();
#pragma unroll 8
        for (int k = 0; k < 128; k++) {
            float4 w = ((float4*)(sW + k * 128))[tx];
#pragma unroll
            for (int i = 0; i < 8; i++) {
                float a = sA[(ty * 8 + i) * 128 + k];
                acc[i][0] += a * w.x; acc[i][1] += a * w.y;
                acc[i][2] += a * w.z; acc[i][3] += a * w.w;
            }
        }
        __syncthreads();
    }

    // write out + per-thread column partials
    float csum[4] = {0.f, 0.f, 0.f, 0.f};
    float csq[4]  = {0.f, 0.f, 0.f, 0.f};
#pragma unroll
    for (int i = 0; i < 8; i++) {
        int gr = r0 + ty * 8 + i;
        if (gr < NN) {
            float4 o = make_float4(acc[i][0], acc[i][1], acc[i][2], acc[i][3]);
            ((float4*)(out + (long)gr * DD))[tx] = o;
#pragma unroll
            for (int j = 0; j < 4; j++) {
                float v = acc[i][j];
                csum[j] += v;
                csq[j]  += v * v;
            }
        }
    }

    // block reduction into smem then one global atomic per column per block
    float* ssum = sA;        // reuse smem (sA no longer needed)
    float* ssq  = sA + 128;
    if (tid < 128) { ssum[tid] = 0.f; ssq[tid] = 0.f; }
    __syncthreads();
#pragma unroll
    for (int j = 0; j < 4; j++) {
        atomicAdd(&ssum[tx * 4 + j], csum[j]);
        atomicAdd(&ssq[tx * 4 + j],  csq[j]);
    }
    __syncthreads();
    if (tid < 128) {
        atomicAdd(&stat[tid],       ssum[tid]);
        atomicAdd(&stat[128 + tid], ssq[tid]);
    }
}

// ---------------------------------------------------------------------------
__global__ void k_bn_finalize(const float* __restrict__ stat,
                              const float* __restrict__ gamma,
                              const float* __restrict__ beta,
                              float* __restrict__ bn) {
    int c = threadIdx.x;
    if (c < 128) {
        float mu  = stat[c] * (1.f / NN);
        float var = stat[128 + c] * (1.f / NN) - mu * mu;
        float sc  = gamma[c] * rsqrtf(var + 1e-5f);
        bn[c]       = sc;
        bn[128 + c] = beta[c] - mu * sc;
    }
}

// final head: out[n,0:2] = relu(h*scale+shift) @ Wm2   (warp per row)
__global__ void __launch_bounds__(256) k_mlp2(
    const float* __restrict__ H, const float* __restrict__ bn,
    const float* __restrict__ Wm2, float* __restrict__ out) {
    __shared__ float sw[256];   // Wm2 [128][2]
    __shared__ float sb[256];   // scale[128], shift[128]
    int tid = threadIdx.x;
    if (tid < 256) { sw[tid] = Wm2[tid]; sb[tid] = bn[tid]; }
    __syncthreads();
    int g = blockIdx.x * blockDim.x + tid;
    int row = g >> 5, lane = g & 31;
    if (row >= NN) return;
    float4 h = ((const float4*)(H + (long)row * DD))[lane];
    float s0 = 0.f, s1 = 0.f;
    int c = lane * 4;
    float hv[4] = {h.x, h.y, h.z, h.w};
#pragma unroll
    for (int j = 0; j < 4; j++) {
        int cc = c + j;
        float v = fmaxf(hv[j] * sb[cc] + sb[128 + cc], 0.f);
        s0 += v * sw[cc * 2];
        s1 += v * sw[cc * 2 + 1];
    }
#pragma unroll
    for (int off = 16; off > 0; off >>= 1) {
        s0 += __shfl_down_sync(0xffffffffu, s0, off);
        s1 += __shfl_down_sync(0xffffffffu, s1, off);
    }
    if (lane == 0) {
        out[row * 2]     = s0;
        out[row * 2 + 1] = s1;
    }
}

// ---------------------------------------------------------------------------
extern "C" void kernel_launch(void* const* d_in, const int* in_sizes, int n_in,
                              void* d_out, int out_size) {
    const float* xA    = (const float*)d_in[0];
    const float* xB    = (const float*)d_in[1];
    const int*   s0    = (const int*)d_in[2];
    const int*   d0    = (const int*)d_in[3];
    const int*   s1    = (const int*)d_in[4];
    const int*   d1    = (const int*)d_in[5];
    const float* W1r0  = (const float*)d_in[6];
    const float* b1r0  = (const float*)d_in[7];
    const float* W1r1  = (const float*)d_in[8];
    const float* b1r1  = (const float*)d_in[9];
    const float* W2r0  = (const float*)d_in[10];
    const float* b2r0  = (const float*)d_in[11];
    const float* W2r1  = (const float*)d_in[12];
    const float* b2r1  = (const float*)d_in[13];
    const float* Wm1   = (const float*)d_in[14];
    const float* gamma = (const float*)d_in[15];
    const float* beta  = (const float*)d_in[16];
    const float* Wm2   = (const float*)d_in[17];
    float* out = (float*)d_out;

    float* S = nullptr;
    cudaGetSymbolAddress((void**)&S, g_s);

    float* AGG1B = S + OFF_AGG1B;
    float* AGG1A = S + OFF_AGG1A;
    float* AGG2B = S + OFF_AGG2B;
    float* AGG2A = S + OFF_AGG2A;
    float* HB    = S + OFF_HB;
    float* HA    = S + OFF_HA;
    float* H2A   = S + OFF_H2A;
    float* H2B   = S + OFF_H2B;
    float* HMLP  = S + OFF_HMLP;
    float* DEG   = S + OFF_DEG;     // [rs_src_r0 | rs_dst_r0 | rs_src_r1 | rs_dst_r1]
    float* STATS = S + OFF_STATS;
    float* BN    = S + OFF_BN;

    static const int SMEM96 = 96 * 1024;
    cudaFuncSetAttribute(k_gemm128, cudaFuncAttributeMaxDynamicSharedMemorySize, SMEM96);
    cudaFuncSetAttribute(k_mlp1,    cudaFuncAttributeMaxDynamicSharedMemorySize, SMEM96);

    // 1) zero accumulators + degrees + stats
    {
        long n4 = 4L * NF / 4;                       // agg buffers
        k_zero<<<(int)((n4 + 255) / 256), 256>>>(AGG1B, n4);
        long n4b = (200000L + 256L) / 4;             // deg + stats
        k_zero<<<(int)((n4b + 255) / 256), 256>>>(DEG, n4b);
    }

    // 2) degrees -> rsqrt
    k_degree<<<(EE + 255) / 256, 256>>>(s0, d0, s1, d1, DEG);
    k_rsqrt<<<(4 * NN + 255) / 256, 256>>>(DEG);

    // 3) conv1 scatters
    int sgrid = (EE * 32 + 255) / 256;
    k_scatter<<<sgrid, 256>>>(xA, s0, d0, DEG + 0 * NN, AGG1B);
    k_scatter<<<sgrid, 256>>>(xB, s1, d1, DEG + 2 * NN, AGG1A);

    // 4) conv1 GEMMs (+bias, relu)
    int ggrid = (NN + 63) / 64;
    k_gemm128<<<ggrid, 256, SMEM96>>>(AGG1B, DEG + 1 * NN, W1r0, b1r0, HB, 1);
    k_gemm128<<<ggrid, 256, SMEM96>>>(AGG1A, DEG + 3 * NN, W1r1, b1r1, HA, 1);

    // 5) conv2 scatters
    k_scatter<<<sgrid, 256>>>(HA, s0, d0, DEG + 0 * NN, AGG2B);
    k_scatter<<<sgrid, 256>>>(HB, s1, d1, DEG + 2 * NN, AGG2A);

    // 6) conv2 GEMMs (+bias, no relu)
    k_gemm128<<<ggrid, 256, SMEM96>>>(AGG2B, DEG + 1 * NN, W2r0, b2r0, H2B, 0);
    k_gemm128<<<ggrid, 256, SMEM96>>>(AGG2A, DEG + 3 * NN, W2r1, b2r1, H2A, 0);

    // 7) MLP layer 1 (implicit concat [H2A | H2B]) + BN stats
    k_mlp1<<<ggrid, 256, SMEM96>>>(H2A, H2B, Wm1, HMLP, STATS);

    // 8) BN affine precompute
    k_bn_finalize<<<1, 128>>>(STATS, gamma, beta, BN);

    // 9) BN + ReLU + final linear
    k_mlp2<<<(NN * 32 + 255) / 256, 256>>>(HMLP, BN, Wm2, out);
}

// round 2
// speedup vs baseline: 1.0301x; 1.0301x over previous
#include <cuda_runtime.h>
#include <math.h>

#define NN 50000
#define EE 600000
#define DD 128
#define NF (NN*DD)

typedef unsigned long long u64;

__device__ __forceinline__ u64 fma2(u64 a, u64 b, u64 c) {
    u64 d;
    asm("fma.rn.f32x2 %0,%1,%2,%3;" : "=l"(d) : "l"(a), "l"(b), "l"(c));
    return d;
}
__device__ __forceinline__ float2 unpack2(u64 v) {
    unsigned lo, hi;
    asm("mov.b64 {%0,%1},%2;" : "=r"(lo), "=r"(hi) : "l"(v));
    return make_float2(__uint_as_float(lo), __uint_as_float(hi));
}

// ---------------------------------------------------------------------------
// float scratch
//  AGG1B,AGG1A,AGG2B,AGG2A,HB,HA,H2A,H2B,HMLP : 9*NF
//  RS: rs_src0, rs_dst0, rs_src1, rs_dst1     : 4*NN
//  STATS: 256, BN: 256
#define OFF_AGG1B 0ULL
#define OFF_AGG1A (1ULL*NF)
#define OFF_AGG2B (2ULL*NF)
#define OFF_AGG2A (3ULL*NF)
#define OFF_HB    (4ULL*NF)
#define OFF_HA    (5ULL*NF)
#define OFF_H2A   (6ULL*NF)
#define OFF_H2B   (7ULL*NF)
#define OFF_HMLP  (8ULL*NF)
#define OFF_RS    (9ULL*NF)
#define OFF_STATS (9ULL*NF + 4ULL*NN)
#define OFF_BN    (OFF_STATS + 256ULL)
#define SCRATCH_FLOATS (OFF_BN + 256ULL)

__device__ __align__(256) float g_s[SCRATCH_FLOATS];

// int scratch: eidx0[EE], eidx1[EE], od0[NN], cnt0[NN], od1[NN], cnt1[NN],
//              rowptr0[NN+1], rowptr1[NN+1], cursor0[NN], cursor1[NN]
#define IOFF_EIDX0 0
#define IOFF_EIDX1 (EE)
#define IOFF_OD0   (2*EE)
#define IOFF_CNT0  (2*EE + NN)
#define IOFF_OD1   (2*EE + 2*NN)
#define IOFF_CNT1  (2*EE + 3*NN)
#define IOFF_RP0   (2*EE + 4*NN)
#define IOFF_RP1   (2*EE + 5*NN + 1)
#define IOFF_CUR0  (2*EE + 6*NN + 2)
#define IOFF_CUR1  (2*EE + 7*NN + 2)
#define SCRATCH_INTS (2*EE + 8*NN + 2)

__device__ __align__(256) int g_i[SCRATCH_INTS];

// ---------------------------------------------------------------------------
__global__ void k_zero(float* __restrict__ p, long n4) {
    long i = (long)blockIdx.x * blockDim.x + threadIdx.x;
    if (i < n4) ((float4*)p)[i] = make_float4(0.f, 0.f, 0.f, 0.f);
}

// histograms: out-degree (src) and in-degree (dst) per relation
__global__ void k_hist(const int* __restrict__ s0, const int* __restrict__ d0,
                       const int* __restrict__ s1, const int* __restrict__ d1,
                       int* __restrict__ od0, int* __restrict__ cnt0,
                       int* __restrict__ od1, int* __restrict__ cnt1) {
    int i = blockIdx.x * blockDim.x + threadIdx.x;
    if (i < EE) {
        atomicAdd(&od0[s0[i]], 1);
        atomicAdd(&cnt0[d0[i]], 1);
        atomicAdd(&od1[s1[i]], 1);
        atomicAdd(&cnt1[d1[i]], 1);
    }
}

// exclusive scan of cnt[NN] -> rowptr (+cursor copy), single block of 1024
__global__ void k_scan(const int* __restrict__ cnt, int* __restrict__ rowptr,
                       int* __restrict__ cursor) {
    __shared__ int sps[1024];
    int t = threadIdx.x;
    const int CH = (NN + 1023) / 1024;
    int base = t * CH;
    int s = 0;
    for (int i = 0; i < CH; i++) {
        int idx = base + i;
        if (idx < NN) s += cnt[idx];
    }
    sps[t] = s;
    __syncthreads();
    for (int off = 1; off < 1024; off <<= 1) {
        int v = (t >= off) ? sps[t - off] : 0;
        __syncthreads();
        sps[t] += v;
        __syncthreads();
    }
    int run = sps[t] - s;  // exclusive
    for (int i = 0; i < CH; i++) {
        int idx = base + i;
        if (idx < NN) {
            rowptr[idx] = run;
            cursor[idx] = run;
            run += cnt[idx];
        }
    }
    if (t == 1023) rowptr[NN] = run;
}

// rs arrays from degree histograms
__global__ void k_rs(const int* __restrict__ od0, const int* __restrict__ cnt0,
                     const int* __restrict__ od1, const int* __restrict__ cnt1,
                     float* __restrict__ rs) {
    int i = blockIdx.x * blockDim.x + threadIdx.x;
    if (i < NN) {
        rs[0 * NN + i] = rsqrtf((float)max(od0[i], 1));
        rs[1 * NN + i] = rsqrtf((float)max(cnt0[i], 1));
        rs[2 * NN + i] = rsqrtf((float)max(od1[i], 1));
        rs[3 * NN + i] = rsqrtf((float)max(cnt1[i], 1));
    }
}

// CSR fill: edge id buckets sorted by dst (stores src node id)
__global__ void k_fill(const int* __restrict__ s0, const int* __restrict__ d0,
                       const int* __restrict__ s1, const int* __restrict__ d1,
                       int* __restrict__ cur0, int* __restrict__ eidx0,
                       int* __restrict__ cur1, int* __restrict__ eidx1) {
    int i = blockIdx.x * blockDim.x + threadIdx.x;
    if (i < EE) {
        int p0 = atomicAdd(&cur0[d0[i]], 1);
        eidx0[p0] = s0[i];
        int p1 = atomicAdd(&cur1[d1[i]], 1);
        eidx1[p1] = s1[i];
    }
}

// ---------------------------------------------------------------------------
// gather: agg[r,:] = sum_{e in row r} x[src_e,:] * (useRs ? rs_src[src_e] : 1)
// one warp per dst row, float4 lanes
__global__ void __launch_bounds__(256) k_gather(
    const float* __restrict__ x, const int* __restrict__ eidx,
    const int* __restrict__ rowptr, const float* __restrict__ rs_src,
    float* __restrict__ agg, int useRs) {
    int g = blockIdx.x * blockDim.x + threadIdx.x;
    int r = g >> 5, lane = g & 31;
    if (r >= NN) return;
    int beg = __ldg(rowptr + r), end = __ldg(rowptr + r + 1);
    float4 acc = make_float4(0.f, 0.f, 0.f, 0.f);
    if (useRs) {
        for (int e = beg; e < end; e++) {
            int s = __ldg(eidx + e);
            float rv = __ldg(rs_src + s);
            float4 v = __ldg((const float4*)(x + (long)s * DD) + lane);
            acc.x += v.x * rv; acc.y += v.y * rv;
            acc.z += v.z * rv; acc.w += v.w * rv;
        }
    } else {
        for (int e = beg; e < end; e++) {
            int s = __ldg(eidx + e);
            float4 v = __ldg((const float4*)(x + (long)s * DD) + lane);
            acc.x += v.x; acc.y += v.y; acc.z += v.z; acc.w += v.w;
        }
    }
    ((float4*)(agg + (long)r * DD))[lane] = acc;
}

// ---------------------------------------------------------------------------
// out[r,:] = act((X[r,:]*rs_in[r]) @ W + b) * (rs_out?rs_out[r]:1)
// 64 rows x 128 cols per block; W transposed in smem (pad 130); f32x2 K-packed
#define WT_STRIDE 130
__global__ void __launch_bounds__(256, 2) k_gemm128(
    const float* __restrict__ X, const float* __restrict__ rs_in,
    const float* __restrict__ W, const float* __restrict__ b,
    float* __restrict__ out, int doRelu, const float* __restrict__ rs_out) {
    extern __shared__ float sm[];
    float* sWT = sm;                       // [128 cols][130]
    float* sA  = sm + 128 * WT_STRIDE;     // [64][128]
    int tid = threadIdx.x;
    int r0 = blockIdx.x * 64;

    // stage W transposed: sWT[c][k] = W[k][c]
    {
        int c = tid & 127, kh = (tid >> 7) * 64;
        float* dst = sWT + c * WT_STRIDE + kh;
        const float* src = W + (long)kh * 128 + c;
        for (int k = 0; k < 64; k++) dst[k] = __ldg(src + k * 128);
    }
    // stage A (scaled by rs_in)
    for (int i = tid; i < 64 * 128 / 4; i += 256) {
        int row = i >> 5;
        int gr = r0 + row;
        float4 v = make_float4(0.f, 0.f, 0.f, 0.f);
        if (gr < NN) {
            v = __ldg((const float4*)(X + (long)gr * DD) + (i & 31));
            float r = __ldg(rs_in + gr);
            v.x *= r; v.y *= r; v.z *= r; v.w *= r;
        }
        ((float4*)sA)[i] = v;
    }
    __syncthreads();

    int lane = tid & 31, wp = tid >> 5;
    int cg = wp & 1, rg = wp >> 1;        // 2 col-groups x 4 row-groups
    int col = cg * 32 + lane;              // this thread: cols {col, col+64}
    int row0 = rg * 16;                    // rows row0..row0+15
    const float* w0 = sWT + col * WT_STRIDE;
    const float* w1 = sWT + (col + 64) * WT_STRIDE;

    u64 acc0[16], acc1[16];
#pragma unroll
    for (int i = 0; i < 16; i++) { acc0[i] = 0ULL; acc1[i] = 0ULL; }

#pragma unroll 2
    for (int k = 0; k < 128; k += 2) {
        u64 wa = *(const u64*)(w0 + k);
        u64 wb = *(const u64*)(w1 + k);
#pragma unroll
        for (int i = 0; i < 16; i++) {
            u64 a2 = *(const u64*)(sA + (row0 + i) * 128 + k);
            acc0[i] = fma2(a2, wa, acc0[i]);
            acc1[i] = fma2(a2, wb, acc1[i]);
        }
    }

    float b0 = __ldg(b + col), b1 = __ldg(b + col + 64);
#pragma unroll
    for (int i = 0; i < 16; i++) {
        int gr = r0 + row0 + i;
        if (gr < NN) {
            float ro = rs_out ? __ldg(rs_out + gr) : 1.f;
            float2 p0 = unpack2(acc0[i]);
            float2 p1 = unpack2(acc1[i]);
            float v0 = p0.x + p0.y + b0;
            float v1 = p1.x + p1.y + b1;
            if (doRelu) { v0 = fmaxf(v0, 0.f); v1 = fmaxf(v1, 0.f); }
            out[(long)gr * DD + col]      = v0 * ro;
            out[(long)gr * DD + col + 64] = v1 * ro;
        }
    }
}

// ---------------------------------------------------------------------------
// MLP layer1 with implicit concat + BN stats
__global__ void __launch_bounds__(256, 2) k_mlp1(
    const float* __restrict__ XA, const float* __restrict__ XB,
    const float* __restrict__ Wm1, float* __restrict__ out,
    float* __restrict__ stat) {
    extern __shared__ float sm[];
    float* sWT = sm;
    float* sA  = sm + 128 * WT_STRIDE;
    int tid = threadIdx.x;
    int r0 = blockIdx.x * 64;
    int lane = tid & 31, wp = tid >> 5;
    int cg = wp & 1, rg = wp >> 1;
    int col = cg * 32 + lane;
    int row0 = rg * 16;

    u64 acc0[16], acc1[16];
#pragma unroll
    for (int i = 0; i < 16; i++) { acc0[i] = 0ULL; acc1[i] = 0ULL; }

    for (int ph = 0; ph < 2; ph++) {
        const float* X = ph ? XB : XA;
        const float* Wp = Wm1 + ph * 128 * 128;
        {
            int c = tid & 127, kh = (tid >> 7) * 64;
            float* dst = sWT + c * WT_STRIDE + kh;
            const float* src = Wp + (long)kh * 128 + c;
            for (int k = 0; k < 64; k++) dst[k] = __ldg(src + k * 128);
        }
        for (int i = tid; i < 64 * 128 / 4; i += 256) {
            int row = i >> 5;
            int gr = r0 + row;
            float4 v = make_float4(0.f, 0.f, 0.f, 0.f);
            if (gr < NN) v = __ldg((const float4*)(X + (long)gr * DD) + (i & 31));
            ((float4*)sA)[i] = v;
        }
        __syncthreads();
        const float* w0 = sWT + col * WT_STRIDE;
        const float* w1 = sWT + (col + 64) * WT_STRIDE;
#pragma unroll 2
        for (int k = 0; k < 128; k += 2) {
            u64 wa = *(const u64*)(w0 + k);
            u64 wb = *(const u64*)(w1 + k);
#pragma unroll
            for (int i = 0; i < 16; i++) {
                u64 a2 = *(const u64*)(sA + (row0 + i) * 128 + k);
                acc0[i] = fma2(a2, wa, acc0[i]);
                acc1[i] = fma2(a2, wb, acc1[i]);
            }
        }
        __syncthreads();
    }

    float cs0 = 0.f, cq0 = 0.f, cs1 = 0.f, cq1 = 0.f;
#pragma unroll
    for (int i = 0; i < 16; i++) {
        int gr = r0 + row0 + i;
        if (gr < NN) {
            float2 p0 = unpack2(acc0[i]);
            float2 p1 = unpack2(acc1[i]);
            float v0 = p0.x + p0.y;
            float v1 = p1.x + p1.y;
            out[(long)gr * DD + col]      = v0;
            out[(long)gr * DD + col + 64] = v1;
            cs0 += v0; cq0 += v0 * v0;
            cs1 += v1; cq1 += v1 * v1;
        }
    }

    float* ssum = sA;
    float* ssq  = sA + 128;
    if (tid < 128) { ssum[tid] = 0.f; ssq[tid] = 0.f; }
    __syncthreads();
    atomicAdd(&ssum[col], cs0);      atomicAdd(&ssq[col], cq0);
    atomicAdd(&ssum[col + 64], cs1); atomicAdd(&ssq[col + 64], cq1);
    __syncthreads();
    if (tid < 128) {
        atomicAdd(&stat[tid], ssum[tid]);
        atomicAdd(&stat[128 + tid], ssq[tid]);
    }
}

// ---------------------------------------------------------------------------
__global__ void k_bn_finalize(const float* __restrict__ stat,
                              const float* __restrict__ gamma,
                              const float* __restrict__ beta,
                              float* __restrict__ bn) {
    int c = threadIdx.x;
    if (c < 128) {
        float mu  = stat[c] * (1.f / NN);
        float var = stat[128 + c] * (1.f / NN) - mu * mu;
        float sc  = gamma[c] * rsqrtf(var + 1e-5f);
        bn[c]       = sc;
        bn[128 + c] = beta[c] - mu * sc;
    }
}

__global__ void __launch_bounds__(256) k_mlp2(
    const float* __restrict__ H, const float* __restrict__ bn,
    const float* __restrict__ Wm2, float* __restrict__ out) {
    __shared__ float sw[256];
    __shared__ float sb[256];
    int tid = threadIdx.x;
    if (tid < 256) { sw[tid] = Wm2[tid]; sb[tid] = bn[tid]; }
    __syncthreads();
    int g = blockIdx.x * blockDim.x + tid;
    int row = g >> 5, lane = g & 31;
    if (row >= NN) return;
    float4 h = ((const float4*)(H + (long)row * DD))[lane];
    float s0 = 0.f, s1 = 0.f;
    int c = lane * 4;
    float hv[4] = {h.x, h.y, h.z, h.w};
#pragma unroll
    for (int j = 0; j < 4; j++) {
        int cc = c + j;
        float v = fmaxf(hv[j] * sb[cc] + sb[128 + cc], 0.f);
        s0 += v * sw[cc * 2];
        s1 += v * sw[cc * 2 + 1];
    }
#pragma unroll
    for (int off = 16; off > 0; off >>= 1) {
        s0 += __shfl_down_sync(0xffffffffu, s0, off);
        s1 += __shfl_down_sync(0xffffffffu, s1, off);
    }
    if (lane == 0) {
        out[row * 2]     = s0;
        out[row * 2 + 1] = s1;
    }
}

// ---------------------------------------------------------------------------
extern "C" void kernel_launch(void* const* d_in, const int* in_sizes, int n_in,
                              void* d_out, int out_size) {
    const float* xA    = (const float*)d_in[0];
    const float* xB    = (const float*)d_in[1];
    const int*   s0    = (const int*)d_in[2];
    const int*   d0    = (const int*)d_in[3];
    const int*   s1    = (const int*)d_in[4];
    const int*   d1    = (const int*)d_in[5];
    const float* W1r0  = (const float*)d_in[6];
    const float* b1r0  = (const float*)d_in[7];
    const float* W1r1  = (const float*)d_in[8];
    const float* b1r1  = (const float*)d_in[9];
    const float* W2r0  = (const float*)d_in[10];
    const float* b2r0  = (const float*)d_in[11];
    const float* W2r1  = (const float*)d_in[12];
    const float* b2r1  = (const float*)d_in[13];
    const float* Wm1   = (const float*)d_in[14];
    const float* gamma = (const float*)d_in[15];
    const float* beta  = (const float*)d_in[16];
    const float* Wm2   = (const float*)d_in[17];
    float* out = (float*)d_out;

    float* S = nullptr;
    cudaGetSymbolAddress((void**)&S, g_s);
    int* I = nullptr;
    cudaGetSymbolAddress((void**)&I, g_i);

    float* AGG1B = S + OFF_AGG1B;
    float* AGG1A = S + OFF_AGG1A;
    float* AGG2B = S + OFF_AGG2B;
    float* AGG2A = S + OFF_AGG2A;
    float* HB    = S + OFF_HB;
    float* HA    = S + OFF_HA;
    float* H2A   = S + OFF_H2A;
    float* H2B   = S + OFF_H2B;
    float* HMLP  = S + OFF_HMLP;
    float* RS    = S + OFF_RS;
    float* STATS = S + OFF_STATS;
    float* BN    = S + OFF_BN;

    int* eidx0 = I + IOFF_EIDX0;
    int* eidx1 = I + IOFF_EIDX1;
    int* od0   = I + IOFF_OD0;
    int* cnt0  = I + IOFF_CNT0;
    int* od1   = I + IOFF_OD1;
    int* cnt1  = I + IOFF_CNT1;
    int* rp0   = I + IOFF_RP0;
    int* rp1   = I + IOFF_RP1;
    int* cur0  = I + IOFF_CUR0;
    int* cur1  = I + IOFF_CUR1;

    float* rs_src0 = RS + 0 * NN;
    float* rs_dst0 = RS + 1 * NN;
    float* rs_src1 = RS + 2 * NN;
    float* rs_dst1 = RS + 3 * NN;

    static const int SMEMB = (128 * WT_STRIDE + 64 * 128) * 4;  // 99328
    cudaFuncSetAttribute(k_gemm128, cudaFuncAttributeMaxDynamicSharedMemorySize, SMEMB);
    cudaFuncSetAttribute(k_mlp1,    cudaFuncAttributeMaxDynamicSharedMemorySize, SMEMB);

    // 1) zero degree histograms (4*NN ints) and STATS (256 floats)
    k_zero<<<(NN + 255) / 256, 256>>>((float*)od0, NN);       // 4*NN ints = NN float4
    k_zero<<<1, 64>>>(STATS, 64);

    // 2) degree histograms
    k_hist<<<(EE + 255) / 256, 256>>>(s0, d0, s1, d1, od0, cnt0, od1, cnt1);

    // 3) CSR rowptr via scan; rs arrays
    k_scan<<<1, 1024>>>(cnt0, rp0, cur0);
    k_scan<<<1, 1024>>>(cnt1, rp1, cur1);
    k_rs<<<(NN + 255) / 256, 256>>>(od0, cnt0, od1, cnt1, RS);

    // 4) CSR fill (src ids bucketed by dst)
    k_fill<<<(EE + 255) / 256, 256>>>(s0, d0, s1, d1, cur0, eidx0, cur1, eidx1);

    int ggrid = (NN * 32 + 255) / 256;   // gathers: warp per dst row
    int mgrid = (NN + 63) / 64;          // gemms

    // 5) conv1 gathers (rs_src applied per edge)
    k_gather<<<ggrid, 256>>>(xA, eidx0, rp0, rs_src0, AGG1B, 1);
    k_gather<<<ggrid, 256>>>(xB, eidx1, rp1, rs_src1, AGG1A, 1);

    // 6) conv1 GEMMs; fold next layer's rs_src into the output
    k_gemm128<<<mgrid, 256, SMEMB>>>(AGG1B, rs_dst0, W1r0, b1r0, HB, 1, rs_src1);
    k_gemm128<<<mgrid, 256, SMEMB>>>(AGG1A, rs_dst1, W1r1, b1r1, HA, 1, rs_src0);

    // 7) conv2 gathers (sources pre-scaled)
    k_gather<<<ggrid, 256>>>(HA, eidx0, rp0, nullptr, AGG2B, 0);
    k_gather<<<ggrid, 256>>>(HB, eidx1, rp1, nullptr, AGG2A, 0);

    // 8) conv2 GEMMs
    k_gemm128<<<mgrid, 256, SMEMB>>>(AGG2B, rs_dst0, W2r0, b2r0, H2B, 0, nullptr);
    k_gemm128<<<mgrid, 256, SMEMB>>>(AGG2A, rs_dst1, W2r1, b2r1, H2A, 0, nullptr);

    // 9) MLP layer 1 (implicit concat [H2A | H2B]) + BN stats
    k_mlp1<<<mgrid, 256, SMEMB>>>(H2A, H2B, Wm1, HMLP, STATS);

    // 10) BN finalize + head
    k_bn_finalize<<<1, 128>>>(STATS, gamma, beta, BN);
    k_mlp2<<<(NN * 32 + 255) / 256, 256>>>(HMLP, BN, Wm2, out);
}

// round 3
// speedup vs baseline: 1.3303x; 1.2914x over previous
#include <cuda_runtime.h>
#include <math.h>

#define NN 50000
#define EE 600000
#define DD 128
#define NF (NN*DD)
#define NBLK 196   // ceil(NN/256)

typedef unsigned long long u64;

__device__ __forceinline__ u64 fma2(u64 a, u64 b, u64 c) {
    u64 d;
    asm("fma.rn.f32x2 %0,%1,%2,%3;" : "=l"(d) : "l"(a), "l"(b), "l"(c));
    return d;
}
__device__ __forceinline__ float2 unpack2(u64 v) {
    unsigned lo, hi;
    asm("mov.b64 {%0,%1},%2;" : "=r"(lo), "=r"(hi) : "l"(v));
    return make_float2(__uint_as_float(lo), __uint_as_float(hi));
}

// ---------------------------------------------------------------------------
#define OFF_AGG1B 0ULL
#define OFF_AGG1A (1ULL*NF)
#define OFF_AGG2B (2ULL*NF)
#define OFF_AGG2A (3ULL*NF)
#define OFF_HB    (4ULL*NF)
#define OFF_HA    (5ULL*NF)
#define OFF_H2A   (6ULL*NF)
#define OFF_H2B   (7ULL*NF)
#define OFF_HMLP  (8ULL*NF)
#define OFF_RS    (9ULL*NF)
#define OFF_STATS (9ULL*NF + 4ULL*NN)
#define OFF_BN    (OFF_STATS + 256ULL)
#define SCRATCH_FLOATS (OFF_BN + 256ULL)

__device__ __align__(256) float g_s[SCRATCH_FLOATS];

#define IOFF_EIDX0 0
#define IOFF_EIDX1 (EE)
#define IOFF_OD0   (2*EE)
#define IOFF_CNT0  (2*EE + NN)
#define IOFF_OD1   (2*EE + 2*NN)
#define IOFF_CNT1  (2*EE + 3*NN)
#define IOFF_RP0   (2*EE + 4*NN)
#define IOFF_RP1   (2*EE + 5*NN + 1)
#define IOFF_CUR0  (2*EE + 6*NN + 2)
#define IOFF_CUR1  (2*EE + 7*NN + 2)
#define IOFF_BSUM  (2*EE + 8*NN + 2)
#define SCRATCH_INTS (IOFF_BSUM + 2*NBLK)

__device__ __align__(256) int g_i[SCRATCH_INTS];

// ---------------------------------------------------------------------------
__global__ void k_zero(float* __restrict__ p, long n4) {
    long i = (long)blockIdx.x * blockDim.x + threadIdx.x;
    if (i < n4) ((float4*)p)[i] = make_float4(0.f, 0.f, 0.f, 0.f);
}

__global__ void k_hist(const int* __restrict__ s0, const int* __restrict__ d0,
                       const int* __restrict__ s1, const int* __restrict__ d1,
                       int* __restrict__ od0, int* __restrict__ cnt0,
                       int* __restrict__ od1, int* __restrict__ cnt1) {
    int i = blockIdx.x * blockDim.x + threadIdx.x;
    if (i < EE) {
        atomicAdd(&od0[s0[i]], 1);
        atomicAdd(&cnt0[d0[i]], 1);
        atomicAdd(&od1[s1[i]], 1);
        atomicAdd(&cnt1[d1[i]], 1);
    }
}

// ---- multi-block scan: pass 1 block sums -----------------------------------
__global__ void k_bsum(const int* __restrict__ c0, const int* __restrict__ c1,
                       int* __restrict__ bsum) {
    const int* cnt = blockIdx.y ? c1 : c0;
    int i = blockIdx.x * 256 + threadIdx.x;
    int v = (i < NN) ? cnt[i] : 0;
    __shared__ int sred[8];
#pragma unroll
    for (int off = 16; off; off >>= 1) v += __shfl_down_sync(0xffffffffu, v, off);
    if ((threadIdx.x & 31) == 0) sred[threadIdx.x >> 5] = v;
    __syncthreads();
    if (threadIdx.x < 8) {
        int s = sred[threadIdx.x];
#pragma unroll
        for (int off = 4; off; off >>= 1) s += __shfl_down_sync(0xffu, s, off);
        if (threadIdx.x == 0) bsum[blockIdx.y * NBLK + blockIdx.x] = s;
    }
}

// ---- pass 2: exclusive scan of the 196 block sums per relation -------------
__global__ void k_bscan(int* __restrict__ bsum) {
    __shared__ int sp[256];
    int t = threadIdx.x;
    int* p = bsum + blockIdx.y * NBLK;
    int v = (t < NBLK) ? p[t] : 0;
    sp[t] = v;
    __syncthreads();
#pragma unroll
    for (int off = 1; off < 256; off <<= 1) {
        int u = (t >= off) ? sp[t - off] : 0;
        __syncthreads();
        sp[t] += u;
        __syncthreads();
    }
    if (t < NBLK) p[t] = sp[t] - v;   // exclusive
}

// ---- pass 3: local exclusive scan + block offset -> rowptr & cursor --------
__global__ void k_rowptr(const int* __restrict__ c0, const int* __restrict__ c1,
                         const int* __restrict__ bsum,
                         int* __restrict__ rp0, int* __restrict__ rp1,
                         int* __restrict__ cur0, int* __restrict__ cur1) {
    const int* cnt = blockIdx.y ? c1 : c0;
    int* rp  = blockIdx.y ? rp1 : rp0;
    int* cur = blockIdx.y ? cur1 : cur0;
    __shared__ int sp[256];
    int t = threadIdx.x;
    int i = blockIdx.x * 256 + t;
    int v = (i < NN) ? cnt[i] : 0;
    sp[t] = v;
    __syncthreads();
#pragma unroll
    for (int off = 1; off < 256; off <<= 1) {
        int u = (t >= off) ? sp[t - off] : 0;
        __syncthreads();
        sp[t] += u;
        __syncthreads();
    }
    if (i < NN) {
        int ex = sp[t] - v + bsum[blockIdx.y * NBLK + blockIdx.x];
        rp[i] = ex;
        cur[i] = ex;
    }
    if (i == NN - 1) rp[NN] = EE;
}

__global__ void k_rs(const int* __restrict__ od0, const int* __restrict__ cnt0,
                     const int* __restrict__ od1, const int* __restrict__ cnt1,
                     float* __restrict__ rs) {
    int i = blockIdx.x * blockDim.x + threadIdx.x;
    if (i < NN) {
        rs[0 * NN + i] = rsqrtf((float)max(od0[i], 1));
        rs[1 * NN + i] = rsqrtf((float)max(cnt0[i], 1));
        rs[2 * NN + i] = rsqrtf((float)max(od1[i], 1));
        rs[3 * NN + i] = rsqrtf((float)max(cnt1[i], 1));
    }
}

__global__ void k_fill(const int* __restrict__ s0, const int* __restrict__ d0,
                       const int* __restrict__ s1, const int* __restrict__ d1,
                       int* __restrict__ cur0, int* __restrict__ eidx0,
                       int* __restrict__ cur1, int* __restrict__ eidx1) {
    int i = blockIdx.x * blockDim.x + threadIdx.x;
    if (i < EE) {
        int p0 = atomicAdd(&cur0[d0[i]], 1);
        eidx0[p0] = s0[i];
        int p1 = atomicAdd(&cur1[d1[i]], 1);
        eidx1[p1] = s1[i];
    }
}

// ---------------------------------------------------------------------------
// gather: agg[r,:] = sum_{e in row r} x[src_e,:] * (useRs ? rs_src[src_e] : 1)
// one warp per dst row, float4 lanes, 2-wide unroll for MLP
__global__ void __launch_bounds__(256) k_gather(
    const float* __restrict__ x, const int* __restrict__ eidx,
    const int* __restrict__ rowptr, const float* __restrict__ rs_src,
    float* __restrict__ agg, int useRs) {
    int g = blockIdx.x * blockDim.x + threadIdx.x;
    int r = g >> 5, lane = g & 31;
    if (r >= NN) return;
    int beg = __ldg(rowptr + r), end = __ldg(rowptr + r + 1);
    float4 acc = make_float4(0.f, 0.f, 0.f, 0.f);
    float4 acc2 = make_float4(0.f, 0.f, 0.f, 0.f);
    int e = beg;
    if (useRs) {
        for (; e + 1 < end; e += 2) {
            int sa = __ldg(eidx + e), sb = __ldg(eidx + e + 1);
            float ra = __ldg(rs_src + sa), rb = __ldg(rs_src + sb);
            float4 va = __ldg((const float4*)(x + (long)sa * DD) + lane);
            float4 vb = __ldg((const float4*)(x + (long)sb * DD) + lane);
            acc.x += va.x * ra; acc.y += va.y * ra;
            acc.z += va.z * ra; acc.w += va.w * ra;
            acc2.x += vb.x * rb; acc2.y += vb.y * rb;
            acc2.z += vb.z * rb; acc2.w += vb.w * rb;
        }
        if (e < end) {
            int sa = __ldg(eidx + e);
            float ra = __ldg(rs_src + sa);
            float4 va = __ldg((const float4*)(x + (long)sa * DD) + lane);
            acc.x += va.x * ra; acc.y += va.y * ra;
            acc.z += va.z * ra; acc.w += va.w * ra;
        }
    } else {
        for (; e + 1 < end; e += 2) {
            int sa = __ldg(eidx + e), sb = __ldg(eidx + e + 1);
            float4 va = __ldg((const float4*)(x + (long)sa * DD) + lane);
            float4 vb = __ldg((const float4*)(x + (long)sb * DD) + lane);
            acc.x += va.x; acc.y += va.y; acc.z += va.z; acc.w += va.w;
            acc2.x += vb.x; acc2.y += vb.y; acc2.z += vb.z; acc2.w += vb.w;
        }
        if (e < end) {
            int sa = __ldg(eidx + e);
            float4 va = __ldg((const float4*)(x + (long)sa * DD) + lane);
            acc.x += va.x; acc.y += va.y; acc.z += va.z; acc.w += va.w;
        }
    }
    acc.x += acc2.x; acc.y += acc2.y; acc.z += acc2.z; acc.w += acc2.w;
    ((float4*)(agg + (long)r * DD))[lane] = acc;
}

// ---------------------------------------------------------------------------
#define WT_STRIDE 130
__global__ void __launch_bounds__(256, 2) k_gemm128(
    const float* __restrict__ X, const float* __restrict__ rs_in,
    const float* __restrict__ W, const float* __restrict__ b,
    float* __restrict__ out, int doRelu, const float* __restrict__ rs_out) {
    extern __shared__ float sm[];
    float* sWT = sm;
    float* sA  = sm + 128 * WT_STRIDE;
    int tid = threadIdx.x;
    int r0 = blockIdx.x * 64;

    {
        int c = tid & 127, kh = (tid >> 7) * 64;
        float* dst = sWT + c * WT_STRIDE + kh;
        const float* src = W + (long)kh * 128 + c;
        for (int k = 0; k < 64; k++) dst[k] = __ldg(src + k * 128);
    }
    for (int i = tid; i < 64 * 128 / 4; i += 256) {
        int row = i >> 5;
        int gr = r0 + row;
        float4 v = make_float4(0.f, 0.f, 0.f, 0.f);
        if (gr < NN) {
            v = __ldg((const float4*)(X + (long)gr * DD) + (i & 31));
            float r = __ldg(rs_in + gr);
            v.x *= r; v.y *= r; v.z *= r; v.w *= r;
        }
        ((float4*)sA)[i] = v;
    }
    __syncthreads();

    int lane = tid & 31, wp = tid >> 5;
    int cg = wp & 1, rg = wp >> 1;
    int col = cg * 32 + lane;
    int row0 = rg * 16;
    const float* w0 = sWT + col * WT_STRIDE;
    const float* w1 = sWT + (col + 64) * WT_STRIDE;

    u64 acc0[16], acc1[16];
#pragma unroll
    for (int i = 0; i < 16; i++) { acc0[i] = 0ULL; acc1[i] = 0ULL; }

#pragma unroll 2
    for (int k = 0; k < 128; k += 2) {
        u64 wa = *(const u64*)(w0 + k);
        u64 wb = *(const u64*)(w1 + k);
#pragma unroll
        for (int i = 0; i < 16; i++) {
            u64 a2 = *(const u64*)(sA + (row0 + i) * 128 + k);
            acc0[i] = fma2(a2, wa, acc0[i]);
            acc1[i] = fma2(a2, wb, acc1[i]);
        }
    }

    float b0 = __ldg(b + col), b1 = __ldg(b + col + 64);
#pragma unroll
    for (int i = 0; i < 16; i++) {
        int gr = r0 + row0 + i;
        if (gr < NN) {
            float ro = rs_out ? __ldg(rs_out + gr) : 1.f;
            float2 p0 = unpack2(acc0[i]);
            float2 p1 = unpack2(acc1[i]);
            float v0 = p0.x + p0.y + b0;
            float v1 = p1.x + p1.y + b1;
            if (doRelu) { v0 = fmaxf(v0, 0.f); v1 = fmaxf(v1, 0.f); }
            out[(long)gr * DD + col]      = v0 * ro;
            out[(long)gr * DD + col + 64] = v1 * ro;
        }
    }
}

// ---------------------------------------------------------------------------
__global__ void __launch_bounds__(256, 2) k_mlp1(
    const float* __restrict__ XA, const float* __restrict__ XB,
    const float* __restrict__ Wm1, float* __restrict__ out,
    float* __restrict__ stat) {
    extern __shared__ float sm[];
    float* sWT = sm;
    float* sA  = sm + 128 * WT_STRIDE;
    int tid = threadIdx.x;
    int r0 = blockIdx.x * 64;
    int lane = tid & 31, wp = tid >> 5;
    int cg = wp & 1, rg = wp >> 1;
    int col = cg * 32 + lane;
    int row0 = rg * 16;

    u64 acc0[16], acc1[16];
#pragma unroll
    for (int i = 0; i < 16; i++) { acc0[i] = 0ULL; acc1[i] = 0ULL; }

    for (int ph = 0; ph < 2; ph++) {
        const float* X = ph ? XB : XA;
        const float* Wp = Wm1 + ph * 128 * 128;
        {
            int c = tid & 127, kh = (tid >> 7) * 64;
            float* dst = sWT + c * WT_STRIDE + kh;
            const float* src = Wp + (long)kh * 128 + c;
            for (int k = 0; k < 64; k++) dst[k] = __ldg(src + k * 128);
        }
        for (int i = tid; i < 64 * 128 / 4; i += 256) {
            int row = i >> 5;
            int gr = r0 + row;
            float4 v = make_float4(0.f, 0.f, 0.f, 0.f);
            if (gr < NN) v = __ldg((const float4*)(X + (long)gr * DD) + (i & 31));
            ((float4*)sA)[i] = v;
        }
        __syncthreads();
        const float* w0 = sWT + col * WT_STRIDE;
        const float* w1 = sWT + (col + 64) * WT_STRIDE;
#pragma unroll 2
        for (int k = 0; k < 128; k += 2) {
            u64 wa = *(const u64*)(w0 + k);
            u64 wb = *(const u64*)(w1 + k);
#pragma unroll
            for (int i = 0; i < 16; i++) {
                u64 a2 = *(const u64*)(sA + (row0 + i) * 128 + k);
                acc0[i] = fma2(a2, wa, acc0[i]);
                acc1[i] = fma2(a2, wb, acc1[i]);
            }
        }
        __syncthreads();
    }

    float cs0 = 0.f, cq0 = 0.f, cs1 = 0.f, cq1 = 0.f;
#pragma unroll
    for (int i = 0; i < 16; i++) {
        int gr = r0 + row0 + i;
        if (gr < NN) {
            float2 p0 = unpack2(acc0[i]);
            float2 p1 = unpack2(acc1[i]);
            float v0 = p0.x + p0.y;
            float v1 = p1.x + p1.y;
            out[(long)gr * DD + col]      = v0;
            out[(long)gr * DD + col + 64] = v1;
            cs0 += v0; cq0 += v0 * v0;
            cs1 += v1; cq1 += v1 * v1;
        }
    }

    float* ssum = sA;
    float* ssq  = sA + 128;
    if (tid < 128) { ssum[tid] = 0.f; ssq[tid] = 0.f; }
    __syncthreads();
    atomicAdd(&ssum[col], cs0);      atomicAdd(&ssq[col], cq0);
    atomicAdd(&ssum[col + 64], cs1); atomicAdd(&ssq[col + 64], cq1);
    __syncthreads();
    if (tid < 128) {
        atomicAdd(&stat[tid], ssum[tid]);
        atomicAdd(&stat[128 + tid], ssq[tid]);
    }
}

// ---------------------------------------------------------------------------
__global__ void k_bn_finalize(const float* __restrict__ stat,
                              const float* __restrict__ gamma,
                              const float* __restrict__ beta,
                              float* __restrict__ bn) {
    int c = threadIdx.x;
    if (c < 128) {
        float mu  = stat[c] * (1.f / NN);
        float var = stat[128 + c] * (1.f / NN) - mu * mu;
        float sc  = gamma[c] * rsqrtf(var + 1e-5f);
        bn[c]       = sc;
        bn[128 + c] = beta[c] - mu * sc;
    }
}

__global__ void __launch_bounds__(256) k_mlp2(
    const float* __restrict__ H, const float* __restrict__ bn,
    const float* __restrict__ Wm2, float* __restrict__ out) {
    __shared__ float sw[256];
    __shared__ float sb[256];
    int tid = threadIdx.x;
    if (tid < 256) { sw[tid] = Wm2[tid]; sb[tid] = bn[tid]; }
    __syncthreads();
    int g = blockIdx.x * blockDim.x + tid;
    int row = g >> 5, lane = g & 31;
    if (row >= NN) return;
    float4 h = ((const float4*)(H + (long)row * DD))[lane];
    float s0 = 0.f, s1 = 0.f;
    int c = lane * 4;
    float hv[4] = {h.x, h.y, h.z, h.w};
#pragma unroll
    for (int j = 0; j < 4; j++) {
        int cc = c + j;
        float v = fmaxf(hv[j] * sb[cc] + sb[128 + cc], 0.f);
        s0 += v * sw[cc * 2];
        s1 += v * sw[cc * 2 + 1];
    }
#pragma unroll
    for (int off = 16; off > 0; off >>= 1) {
        s0 += __shfl_down_sync(0xffffffffu, s0, off);
        s1 += __shfl_down_sync(0xffffffffu, s1, off);
    }
    if (lane == 0) {
        out[row * 2]     = s0;
        out[row * 2 + 1] = s1;
    }
}

// ---------------------------------------------------------------------------
extern "C" void kernel_launch(void* const* d_in, const int* in_sizes, int n_in,
                              void* d_out, int out_size) {
    const float* xA    = (const float*)d_in[0];
    const float* xB    = (const float*)d_in[1];
    const int*   s0    = (const int*)d_in[2];
    const int*   d0    = (const int*)d_in[3];
    const int*   s1    = (const int*)d_in[4];
    const int*   d1    = (const int*)d_in[5];
    const float* W1r0  = (const float*)d_in[6];
    const float* b1r0  = (const float*)d_in[7];
    const float* W1r1  = (const float*)d_in[8];
    const float* b1r1  = (const float*)d_in[9];
    const float* W2r0  = (const float*)d_in[10];
    const float* b2r0  = (const float*)d_in[11];
    const float* W2r1  = (const float*)d_in[12];
    const float* b2r1  = (const float*)d_in[13];
    const float* Wm1   = (const float*)d_in[14];
    const float* gamma = (const float*)d_in[15];
    const float* beta  = (const float*)d_in[16];
    const float* Wm2   = (const float*)d_in[17];
    float* out = (float*)d_out;

    float* S = nullptr;
    cudaGetSymbolAddress((void**)&S, g_s);
    int* I = nullptr;
    cudaGetSymbolAddress((void**)&I, g_i);

    float* AGG1B = S + OFF_AGG1B;
    float* AGG1A = S + OFF_AGG1A;
    float* AGG2B = S + OFF_AGG2B;
    float* AGG2A = S + OFF_AGG2A;
    float* HB    = S + OFF_HB;
    float* HA    = S + OFF_HA;
    float* H2A   = S + OFF_H2A;
    float* H2B   = S + OFF_H2B;
    float* HMLP  = S + OFF_HMLP;
    float* RS    = S + OFF_RS;
    float* STATS = S + OFF_STATS;
    float* BN    = S + OFF_BN;

    int* eidx0 = I + IOFF_EIDX0;
    int* eidx1 = I + IOFF_EIDX1;
    int* od0   = I + IOFF_OD0;
    int* cnt0  = I + IOFF_CNT0;
    int* od1   = I + IOFF_OD1;
    int* cnt1  = I + IOFF_CNT1;
    int* rp0   = I + IOFF_RP0;
    int* rp1   = I + IOFF_RP1;
    int* cur0  = I + IOFF_CUR0;
    int* cur1  = I + IOFF_CUR1;
    int* bsum  = I + IOFF_BSUM;

    float* rs_src0 = RS + 0 * NN;
    float* rs_dst0 = RS + 1 * NN;
    float* rs_src1 = RS + 2 * NN;
    float* rs_dst1 = RS + 3 * NN;

    static const int SMEMB = (128 * WT_STRIDE + 64 * 128) * 4;
    cudaFuncSetAttribute(k_gemm128, cudaFuncAttributeMaxDynamicSharedMemorySize, SMEMB);
    cudaFuncSetAttribute(k_mlp1,    cudaFuncAttributeMaxDynamicSharedMemorySize, SMEMB);

    // 1) zero degree histograms + STATS
    k_zero<<<(NN + 255) / 256, 256>>>((float*)od0, NN);  // 4*NN ints
    k_zero<<<1, 64>>>(STATS, 64);

    // 2) degree histograms
    k_hist<<<(EE + 255) / 256, 256>>>(s0, d0, s1, d1, od0, cnt0, od1, cnt1);

    // 3) multi-block scan (both relations in parallel) + rs arrays
    {
        dim3 gb(NBLK, 2);
        k_bsum<<<gb, 256>>>(cnt0, cnt1, bsum);
        k_bscan<<<dim3(1, 2), 256>>>(bsum);
        k_rowptr<<<gb, 256>>>(cnt0, cnt1, bsum, rp0, rp1, cur0, cur1);
    }
    k_rs<<<(NN + 255) / 256, 256>>>(od0, cnt0, od1, cnt1, RS);

    // 4) CSR fill
    k_fill<<<(EE + 255) / 256, 256>>>(s0, d0, s1, d1, cur0, eidx0, cur1, eidx1);

    int ggrid = (NN * 32 + 255) / 256;
    int mgrid = (NN + 63) / 64;

    // 5) conv1 gathers
    k_gather<<<ggrid, 256>>>(xA, eidx0, rp0, rs_src0, AGG1B, 1);
    k_gather<<<ggrid, 256>>>(xB, eidx1, rp1, rs_src1, AGG1A, 1);

    // 6) conv1 GEMMs (fold next layer's rs_src into outputs)
    k_gemm128<<<mgrid, 256, SMEMB>>>(AGG1B, rs_dst0, W1r0, b1r0, HB, 1, rs_src1);
    k_gemm128<<<mgrid, 256, SMEMB>>>(AGG1A, rs_dst1, W1r1, b1r1, HA, 1, rs_src0);

    // 7) conv2 gathers
    k_gather<<<ggrid, 256>>>(HA, eidx0, rp0, nullptr, AGG2B, 0);
    k_gather<<<ggrid, 256>>>(HB, eidx1, rp1, nullptr, AGG2A, 0);

    // 8) conv2 GEMMs
    k_gemm128<<<mgrid, 256, SMEMB>>>(AGG2B, rs_dst0, W2r0, b2r0, H2B, 0, nullptr);
    k_gemm128<<<mgrid, 256, SMEMB>>>(AGG2A, rs_dst1, W2r1, b2r1, H2A, 0, nullptr);

    // 9) MLP layer 1 + BN stats
    k_mlp1<<<mgrid, 256, SMEMB>>>(H2A, H2B, Wm1, HMLP, STATS);

    // 10) BN finalize + head
    k_bn_finalize<<<1, 128>>>(STATS, gamma, beta, BN);
    k_mlp2<<<(NN * 32 + 255) / 256, 256>>>(HMLP, BN, Wm2, out);
}

// round 4
// speedup vs baseline: 1.4077x; 1.0582x over previous
#include <cuda_runtime.h>
#include <math.h>

#define NN 50000
#define EE 600000
#define DD 128
#define NF (NN*DD)
#define NBLK 196   // ceil(NN/256)

// ---------------------------------------------------------------------------
// tf32 helpers
__device__ __forceinline__ unsigned f2tf(float f) {
    unsigned r;
    asm("cvt.rna.tf32.f32 %0, %1;" : "=r"(r) : "f"(f));
    return r;
}
__device__ __forceinline__ void mma_tf32(
    float& d0, float& d1, float& d2, float& d3,
    unsigned a0, unsigned a1, unsigned a2, unsigned a3,
    unsigned b0, unsigned b1) {
    asm volatile(
        "mma.sync.aligned.m16n8k8.row.col.f32.tf32.tf32.f32 "
        "{%0,%1,%2,%3},{%4,%5,%6,%7},{%8,%9},{%0,%1,%2,%3};"
        : "+f"(d0), "+f"(d1), "+f"(d2), "+f"(d3)
        : "r"(a0), "r"(a1), "r"(a2), "r"(a3), "r"(b0), "r"(b1));
}

// ---------------------------------------------------------------------------
#define OFF_AGG1B 0ULL
#define OFF_AGG1A (1ULL*NF)
#define OFF_AGG2B (2ULL*NF)
#define OFF_AGG2A (3ULL*NF)
#define OFF_HB    (4ULL*NF)
#define OFF_HA    (5ULL*NF)
#define OFF_H2A   (6ULL*NF)
#define OFF_H2B   (7ULL*NF)
#define OFF_HMLP  (8ULL*NF)
#define OFF_RS    (9ULL*NF)
#define OFF_STATS (9ULL*NF + 4ULL*NN)
#define OFF_BN    (OFF_STATS + 256ULL)
#define OFF_WT    (OFF_BN + 256ULL)
#define SCRATCH_FLOATS (OFF_WT + 196608ULL)

__device__ __align__(256) float g_s[SCRATCH_FLOATS];

#define IOFF_EIDX0 0
#define IOFF_EIDX1 (EE)
#define IOFF_OD0   (2*EE)
#define IOFF_CNT0  (2*EE + NN)
#define IOFF_OD1   (2*EE + 2*NN)
#define IOFF_CNT1  (2*EE + 3*NN)
#define IOFF_RP0   (2*EE + 4*NN)
#define IOFF_RP1   (2*EE + 5*NN + 1)
#define IOFF_CUR0  (2*EE + 6*NN + 2)
#define IOFF_CUR1  (2*EE + 7*NN + 2)
#define IOFF_BSUM  (2*EE + 8*NN + 2)
#define SCRATCH_INTS (IOFF_BSUM + 2*NBLK)

__device__ __align__(256) int g_i[SCRATCH_INTS];

// ---------------------------------------------------------------------------
__global__ void k_zero(float* __restrict__ p, long n4) {
    long i = (long)blockIdx.x * blockDim.x + threadIdx.x;
    if (i < n4) ((float4*)p)[i] = make_float4(0.f, 0.f, 0.f, 0.f);
}

__global__ void k_hist(const int* __restrict__ s0, const int* __restrict__ d0,
                       const int* __restrict__ s1, const int* __restrict__ d1,
                       int* __restrict__ od0, int* __restrict__ cnt0,
                       int* __restrict__ od1, int* __restrict__ cnt1) {
    int i = blockIdx.x * blockDim.x + threadIdx.x;
    if (i < EE) {
        atomicAdd(&od0[s0[i]], 1);
        atomicAdd(&cnt0[d0[i]], 1);
        atomicAdd(&od1[s1[i]], 1);
        atomicAdd(&cnt1[d1[i]], 1);
    }
}

__global__ void k_bsum(const int* __restrict__ c0, const int* __restrict__ c1,
                       int* __restrict__ bsum) {
    const int* cnt = blockIdx.y ? c1 : c0;
    int i = blockIdx.x * 256 + threadIdx.x;
    int v = (i < NN) ? cnt[i] : 0;
    __shared__ int sred[8];
#pragma unroll
    for (int off = 16; off; off >>= 1) v += __shfl_down_sync(0xffffffffu, v, off);
    if ((threadIdx.x & 31) == 0) sred[threadIdx.x >> 5] = v;
    __syncthreads();
    if (threadIdx.x < 8) {
        int s = sred[threadIdx.x];
#pragma unroll
        for (int off = 4; off; off >>= 1) s += __shfl_down_sync(0xffu, s, off);
        if (threadIdx.x == 0) bsum[blockIdx.y * NBLK + blockIdx.x] = s;
    }
}

__global__ void k_bscan(int* __restrict__ bsum) {
    __shared__ int sp[256];
    int t = threadIdx.x;
    int* p = bsum + blockIdx.y * NBLK;
    int v = (t < NBLK) ? p[t] : 0;
    sp[t] = v;
    __syncthreads();
#pragma unroll
    for (int off = 1; off < 256; off <<= 1) {
        int u = (t >= off) ? sp[t - off] : 0;
        __syncthreads();
        sp[t] += u;
        __syncthreads();
    }
    if (t < NBLK) p[t] = sp[t] - v;
}

__global__ void k_rowptr(const int* __restrict__ c0, const int* __restrict__ c1,
                         const int* __restrict__ bsum,
                         int* __restrict__ rp0, int* __restrict__ rp1,
                         int* __restrict__ cur0, int* __restrict__ cur1) {
    const int* cnt = blockIdx.y ? c1 : c0;
    int* rp  = blockIdx.y ? rp1 : rp0;
    int* cur = blockIdx.y ? cur1 : cur0;
    __shared__ int sp[256];
    int t = threadIdx.x;
    int i = blockIdx.x * 256 + t;
    int v = (i < NN) ? cnt[i] : 0;
    sp[t] = v;
    __syncthreads();
#pragma unroll
    for (int off = 1; off < 256; off <<= 1) {
        int u = (t >= off) ? sp[t - off] : 0;
        __syncthreads();
        sp[t] += u;
        __syncthreads();
    }
    if (i < NN) {
        int ex = sp[t] - v + bsum[blockIdx.y * NBLK + blockIdx.x];
        rp[i] = ex;
        cur[i] = ex;
    }
    if (i == NN - 1) rp[NN] = EE;
}

__global__ void k_rs(const int* __restrict__ od0, const int* __restrict__ cnt0,
                     const int* __restrict__ od1, const int* __restrict__ cnt1,
                     float* __restrict__ rs) {
    int i = blockIdx.x * blockDim.x + threadIdx.x;
    if (i < NN) {
        rs[0 * NN + i] = rsqrtf((float)max(od0[i], 1));
        rs[1 * NN + i] = rsqrtf((float)max(cnt0[i], 1));
        rs[2 * NN + i] = rsqrtf((float)max(od1[i], 1));
        rs[3 * NN + i] = rsqrtf((float)max(cnt1[i], 1));
    }
}

__global__ void k_fill(const int* __restrict__ s0, const int* __restrict__ d0,
                       const int* __restrict__ s1, const int* __restrict__ d1,
                       int* __restrict__ cur0, int* __restrict__ eidx0,
                       int* __restrict__ cur1, int* __restrict__ eidx1) {
    int i = blockIdx.x * blockDim.x + threadIdx.x;
    if (i < EE) {
        int p0 = atomicAdd(&cur0[d0[i]], 1);
        eidx0[p0] = s0[i];
        int p1 = atomicAdd(&cur1[d1[i]], 1);
        eidx1[p1] = s1[i];
    }
}

// weight prep: transpose + tf32 hi/lo split, once per launch
__global__ void k_wprep(const float* __restrict__ W1r0, const float* __restrict__ W1r1,
                        const float* __restrict__ W2r0, const float* __restrict__ W2r1,
                        const float* __restrict__ Wm1, float* __restrict__ WT) {
    int idx = blockIdx.x * 256 + threadIdx.x;
    if (idx < 65536) {
        int mat = idx >> 14, r = idx & 16383;
        int n = r & 127, k = r >> 7;
        const float* Wsrc = (mat == 0) ? W1r0 : (mat == 1) ? W1r1 :
                            (mat == 2) ? W2r0 : W2r1;
        float v = __ldg(Wsrc + k * 128 + n);
        unsigned h = f2tf(v);
        float lo = v - __uint_as_float(h);
        WT[mat * 32768 + n * 128 + k]         = __uint_as_float(h);
        WT[mat * 32768 + 16384 + n * 128 + k] = __uint_as_float(f2tf(lo));
    } else if (idx < 98304) {
        int r = idx - 65536;
        int n = r & 127, k = r >> 7;   // k 0..255
        float v = __ldg(Wm1 + k * 128 + n);
        unsigned h = f2tf(v);
        float lo = v - __uint_as_float(h);
        WT[131072 + n * 256 + k]         = __uint_as_float(h);
        WT[131072 + 32768 + n * 256 + k] = __uint_as_float(f2tf(lo));
    }
}

// ---------------------------------------------------------------------------
// gather (unchanged)
__global__ void __launch_bounds__(256) k_gather(
    const float* __restrict__ x, const int* __restrict__ eidx,
    const int* __restrict__ rowptr, const float* __restrict__ rs_src,
    float* __restrict__ agg, int useRs) {
    int g = blockIdx.x * blockDim.x + threadIdx.x;
    int r = g >> 5, lane = g & 31;
    if (r >= NN) return;
    int beg = __ldg(rowptr + r), end = __ldg(rowptr + r + 1);
    float4 acc = make_float4(0.f, 0.f, 0.f, 0.f);
    float4 acc2 = make_float4(0.f, 0.f, 0.f, 0.f);
    int e = beg;
    if (useRs) {
        for (; e + 1 < end; e += 2) {
            int sa = __ldg(eidx + e), sb = __ldg(eidx + e + 1);
            float ra = __ldg(rs_src + sa), rb = __ldg(rs_src + sb);
            float4 va = __ldg((const float4*)(x + (long)sa * DD) + lane);
            float4 vb = __ldg((const float4*)(x + (long)sb * DD) + lane);
            acc.x += va.x * ra; acc.y += va.y * ra;
            acc.z += va.z * ra; acc.w += va.w * ra;
            acc2.x += vb.x * rb; acc2.y += vb.y * rb;
            acc2.z += vb.z * rb; acc2.w += vb.w * rb;
        }
        if (e < end) {
            int sa = __ldg(eidx + e);
            float ra = __ldg(rs_src + sa);
            float4 va = __ldg((const float4*)(x + (long)sa * DD) + lane);
            acc.x += va.x * ra; acc.y += va.y * ra;
            acc.z += va.z * ra; acc.w += va.w * ra;
        }
    } else {
        for (; e + 1 < end; e += 2) {
            int sa = __ldg(eidx + e), sb = __ldg(eidx + e + 1);
            float4 va = __ldg((const float4*)(x + (long)sa * DD) + lane);
            float4 vb = __ldg((const float4*)(x + (long)sb * DD) + lane);
            acc.x += va.x; acc.y += va.y; acc.z += va.z; acc.w += va.w;
            acc2.x += vb.x; acc2.y += vb.y; acc2.z += vb.z; acc2.w += vb.w;
        }
        if (e < end) {
            int sa = __ldg(eidx + e);
            float4 va = __ldg((const float4*)(x + (long)sa * DD) + lane);
            acc.x += va.x; acc.y += va.y; acc.z += va.z; acc.w += va.w;
        }
    }
    acc.x += acc2.x; acc.y += acc2.y; acc.z += acc2.z; acc.w += acc2.w;
    ((float4*)(agg + (long)r * DD))[lane] = acc;
}

// ---------------------------------------------------------------------------
// TF32 tensor-core GEMM: out[r,:] = act((X[r,:]*rs_in[r]) @ W + b) * rs_out[r]
// tile 128x128, K chunks of 64. smem stride 68 floats (conflict-free frags).
// WT: pre-transposed hi plane [n][k] at +0, lo plane at +16384.
#define SSTRIDE 68
#define SM_AHI 0
#define SM_ALO 8704
#define SM_WHI 17408
#define SM_WLO 26112
#define SMEM_T ((size_t)34816 * 4)

__global__ void __launch_bounds__(256, 1) k_gemm_tf32(
    const float* __restrict__ X, const float* __restrict__ rs_in,
    const float* __restrict__ WT, const float* __restrict__ b,
    float* __restrict__ out, int doRelu, const float* __restrict__ rs_out) {
    extern __shared__ float sm[];
    float* sAhi = sm + SM_AHI;
    float* sAlo = sm + SM_ALO;
    float* sWhi = sm + SM_WHI;
    float* sWlo = sm + SM_WLO;
    int tid = threadIdx.x;
    int r0 = blockIdx.x * 128;
    int lane = tid & 31, w = tid >> 5;
    int mg = w >> 2, ng = w & 3;
    int tg = lane & 3, gid = lane >> 2;

    float acc[4][4][4];
#pragma unroll
    for (int mi = 0; mi < 4; mi++)
#pragma unroll
        for (int ni = 0; ni < 4; ni++)
#pragma unroll
            for (int q = 0; q < 4; q++) acc[mi][ni][q] = 0.f;

    for (int kc = 0; kc < 2; kc++) {
        // stage A (scaled, hi/lo split)
        for (int i = tid; i < 2048; i += 256) {
            int row = i >> 4, k4 = i & 15;
            int gr = r0 + row;
            float4 v = make_float4(0.f, 0.f, 0.f, 0.f);
            if (gr < NN) {
                v = __ldg((const float4*)(X + (long)gr * DD + kc * 64) + k4);
                float r = __ldg(rs_in + gr);
                v.x *= r; v.y *= r; v.z *= r; v.w *= r;
            }
            unsigned h0 = f2tf(v.x), h1 = f2tf(v.y), h2 = f2tf(v.z), h3 = f2tf(v.w);
            float4 hv = make_float4(__uint_as_float(h0), __uint_as_float(h1),
                                    __uint_as_float(h2), __uint_as_float(h3));
            float4 lv = make_float4(
                __uint_as_float(f2tf(v.x - hv.x)), __uint_as_float(f2tf(v.y - hv.y)),
                __uint_as_float(f2tf(v.z - hv.z)), __uint_as_float(f2tf(v.w - hv.w)));
            *(float4*)(sAhi + row * SSTRIDE + k4 * 4) = hv;
            *(float4*)(sAlo + row * SSTRIDE + k4 * 4) = lv;
        }
        // stage W (plain copies of pre-split planes)
        for (int i = tid; i < 2048; i += 256) {
            int n = i >> 4, k4 = i & 15;
            *(float4*)(sWhi + n * SSTRIDE + k4 * 4) =
                __ldg((const float4*)(WT + n * 128 + kc * 64) + k4);
            *(float4*)(sWlo + n * SSTRIDE + k4 * 4) =
                __ldg((const float4*)(WT + 16384 + n * 128 + kc * 64) + k4);
        }
        __syncthreads();

        for (int ks = 0; ks < 8; ks++) {
            int k0 = ks * 8 + tg;
            unsigned Ah[4][4], Al[4][4], Bh[4][2], Bl[4][2];
#pragma unroll
            for (int mi = 0; mi < 4; mi++) {
                int rb = (mg * 64 + mi * 16 + gid) * SSTRIDE;
                Ah[mi][0] = __float_as_uint(sAhi[rb + k0]);
                Ah[mi][1] = __float_as_uint(sAhi[rb + 8 * SSTRIDE + k0]);
                Ah[mi][2] = __float_as_uint(sAhi[rb + k0 + 4]);
                Ah[mi][3] = __float_as_uint(sAhi[rb + 8 * SSTRIDE + k0 + 4]);
                Al[mi][0] = __float_as_uint(sAlo[rb + k0]);
                Al[mi][1] = __float_as_uint(sAlo[rb + 8 * SSTRIDE + k0]);
                Al[mi][2] = __float_as_uint(sAlo[rb + k0 + 4]);
                Al[mi][3] = __float_as_uint(sAlo[rb + 8 * SSTRIDE + k0 + 4]);
            }
#pragma unroll
            for (int ni = 0; ni < 4; ni++) {
                int cb = (ng * 32 + ni * 8 + gid) * SSTRIDE;
                Bh[ni][0] = __float_as_uint(sWhi[cb + k0]);
                Bh[ni][1] = __float_as_uint(sWhi[cb + k0 + 4]);
                Bl[ni][0] = __float_as_uint(sWlo[cb + k0]);
                Bl[ni][1] = __float_as_uint(sWlo[cb + k0 + 4]);
            }
#pragma unroll
            for (int mi = 0; mi < 4; mi++)
#pragma unroll
                for (int ni = 0; ni < 4; ni++) {
                    float* d = acc[mi][ni];
                    mma_tf32(d[0], d[1], d[2], d[3],
                             Ah[mi][0], Ah[mi][1], Ah[mi][2], Ah[mi][3],
                             Bh[ni][0], Bh[ni][1]);
                    mma_tf32(d[0], d[1], d[2], d[3],
                             Ah[mi][0], Ah[mi][1], Ah[mi][2], Ah[mi][3],
                             Bl[ni][0], Bl[ni][1]);
                    mma_tf32(d[0], d[1], d[2], d[3],
                             Al[mi][0], Al[mi][1], Al[mi][2], Al[mi][3],
                             Bh[ni][0], Bh[ni][1]);
                }
        }
        __syncthreads();
    }

    // epilogue
#pragma unroll
    for (int ni = 0; ni < 4; ni++) {
        int col = ng * 32 + ni * 8 + 2 * tg;
        float b0 = __ldg(b + col), b1 = __ldg(b + col + 1);
#pragma unroll
        for (int mi = 0; mi < 4; mi++) {
            int gr = r0 + mg * 64 + mi * 16 + gid;
            if (gr < NN) {
                float ro = rs_out ? __ldg(rs_out + gr) : 1.f;
                float v0 = acc[mi][ni][0] + b0;
                float v1 = acc[mi][ni][1] + b1;
                if (doRelu) { v0 = fmaxf(v0, 0.f); v1 = fmaxf(v1, 0.f); }
                *(float2*)(out + (long)gr * DD + col) = make_float2(v0 * ro, v1 * ro);
            }
            int gr8 = gr + 8;
            if (gr8 < NN) {
                float ro = rs_out ? __ldg(rs_out + gr8) : 1.f;
                float v2 = acc[mi][ni][2] + b0;
                float v3 = acc[mi][ni][3] + b1;
                if (doRelu) { v2 = fmaxf(v2, 0.f); v3 = fmaxf(v3, 0.f); }
                *(float2*)(out + (long)gr8 * DD + col) = make_float2(v2 * ro, v3 * ro);
            }
        }
    }
}

// ---------------------------------------------------------------------------
// MLP layer1 (implicit concat) in TF32 + BN stats
__global__ void __launch_bounds__(256, 1) k_mlp1_tf32(
    const float* __restrict__ XA, const float* __restrict__ XB,
    const float* __restrict__ WTm1, float* __restrict__ out,
    float* __restrict__ stat) {
    extern __shared__ float sm[];
    float* sAhi = sm + SM_AHI;
    float* sAlo = sm + SM_ALO;
    float* sWhi = sm + SM_WHI;
    float* sWlo = sm + SM_WLO;
    int tid = threadIdx.x;
    int r0 = blockIdx.x * 128;
    int lane = tid & 31, w = tid >> 5;
    int mg = w >> 2, ng = w & 3;
    int tg = lane & 3, gid = lane >> 2;

    float acc[4][4][4];
#pragma unroll
    for (int mi = 0; mi < 4; mi++)
#pragma unroll
        for (int ni = 0; ni < 4; ni++)
#pragma unroll
            for (int q = 0; q < 4; q++) acc[mi][ni][q] = 0.f;

    for (int ph = 0; ph < 2; ph++) {
        const float* X = ph ? XB : XA;
        for (int kc = 0; kc < 2; kc++) {
            for (int i = tid; i < 2048; i += 256) {
                int row = i >> 4, k4 = i & 15;
                int gr = r0 + row;
                float4 v = make_float4(0.f, 0.f, 0.f, 0.f);
                if (gr < NN)
                    v = __ldg((const float4*)(X + (long)gr * DD + kc * 64) + k4);
                unsigned h0 = f2tf(v.x), h1 = f2tf(v.y), h2 = f2tf(v.z), h3 = f2tf(v.w);
                float4 hv = make_float4(__uint_as_float(h0), __uint_as_float(h1),
                                        __uint_as_float(h2), __uint_as_float(h3));
                float4 lv = make_float4(
                    __uint_as_float(f2tf(v.x - hv.x)), __uint_as_float(f2tf(v.y - hv.y)),
                    __uint_as_float(f2tf(v.z - hv.z)), __uint_as_float(f2tf(v.w - hv.w)));
                *(float4*)(sAhi + row * SSTRIDE + k4 * 4) = hv;
                *(float4*)(sAlo + row * SSTRIDE + k4 * 4) = lv;
            }
            for (int i = tid; i < 2048; i += 256) {
                int n = i >> 4, k4 = i & 15;
                *(float4*)(sWhi + n * SSTRIDE + k4 * 4) =
                    __ldg((const float4*)(WTm1 + n * 256 + ph * 128 + kc * 64) + k4);
                *(float4*)(sWlo + n * SSTRIDE + k4 * 4) =
                    __ldg((const float4*)(WTm1 + 32768 + n * 256 + ph * 128 + kc * 64) + k4);
            }
            __syncthreads();

            for (int ks = 0; ks < 8; ks++) {
                int k0 = ks * 8 + tg;
                unsigned Ah[4][4], Al[4][4], Bh[4][2], Bl[4][2];
#pragma unroll
                for (int mi = 0; mi < 4; mi++) {
                    int rb = (mg * 64 + mi * 16 + gid) * SSTRIDE;
                    Ah[mi][0] = __float_as_uint(sAhi[rb + k0]);
                    Ah[mi][1] = __float_as_uint(sAhi[rb + 8 * SSTRIDE + k0]);
                    Ah[mi][2] = __float_as_uint(sAhi[rb + k0 + 4]);
                    Ah[mi][3] = __float_as_uint(sAhi[rb + 8 * SSTRIDE + k0 + 4]);
                    Al[mi][0] = __float_as_uint(sAlo[rb + k0]);
                    Al[mi][1] = __float_as_uint(sAlo[rb + 8 * SSTRIDE + k0]);
                    Al[mi][2] = __float_as_uint(sAlo[rb + k0 + 4]);
                    Al[mi][3] = __float_as_uint(sAlo[rb + 8 * SSTRIDE + k0 + 4]);
                }
#pragma unroll
                for (int ni = 0; ni < 4; ni++) {
                    int cb = (ng * 32 + ni * 8 + gid) * SSTRIDE;
                    Bh[ni][0] = __float_as_uint(sWhi[cb + k0]);
                    Bh[ni][1] = __float_as_uint(sWhi[cb + k0 + 4]);
                    Bl[ni][0] = __float_as_uint(sWlo[cb + k0]);
                    Bl[ni][1] = __float_as_uint(sWlo[cb + k0 + 4]);
                }
#pragma unroll
                for (int mi = 0; mi < 4; mi++)
#pragma unroll
                    for (int ni = 0; ni < 4; ni++) {
                        float* d = acc[mi][ni];
                        mma_tf32(d[0], d[1], d[2], d[3],
                                 Ah[mi][0], Ah[mi][1], Ah[mi][2], Ah[mi][3],
                                 Bh[ni][0], Bh[ni][1]);
                        mma_tf32(d[0], d[1], d[2], d[3],
                                 Ah[mi][0], Ah[mi][1], Ah[mi][2], Ah[mi][3],
                                 Bl[ni][0], Bl[ni][1]);
                        mma_tf32(d[0], d[1], d[2], d[3],
                                 Al[mi][0], Al[mi][1], Al[mi][2], Al[mi][3],
                                 Bh[ni][0], Bh[ni][1]);
                    }
            }
            __syncthreads();
        }
    }

    // epilogue + BN stats
    float cs[4][2], cq[4][2];
#pragma unroll
    for (int ni = 0; ni < 4; ni++) {
        cs[ni][0] = cs[ni][1] = 0.f;
        cq[ni][0] = cq[ni][1] = 0.f;
    }
#pragma unroll
    for (int ni = 0; ni < 4; ni++) {
        int col = ng * 32 + ni * 8 + 2 * tg;
#pragma unroll
        for (int mi = 0; mi < 4; mi++) {
            int gr = r0 + mg * 64 + mi * 16 + gid;
            if (gr < NN) {
                float v0 = acc[mi][ni][0], v1 = acc[mi][ni][1];
                *(float2*)(out + (long)gr * DD + col) = make_float2(v0, v1);
                cs[ni][0] += v0; cq[ni][0] += v0 * v0;
                cs[ni][1] += v1; cq[ni][1] += v1 * v1;
            }
            int gr8 = gr + 8;
            if (gr8 < NN) {
                float v2 = acc[mi][ni][2], v3 = acc[mi][ni][3];
                *(float2*)(out + (long)gr8 * DD + col) = make_float2(v2, v3);
                cs[ni][0] += v2; cq[ni][0] += v2 * v2;
                cs[ni][1] += v3; cq[ni][1] += v3 * v3;
            }
        }
    }
    __syncthreads();
    float* ssum = sm;          // reuse smem
    float* ssq  = sm + 128;
    if (tid < 256) sm[tid] = 0.f;
    __syncthreads();
#pragma unroll
    for (int ni = 0; ni < 4; ni++) {
        int col = ng * 32 + ni * 8 + 2 * tg;
        atomicAdd(&ssum[col], cs[ni][0]);
        atomicAdd(&ssum[col + 1], cs[ni][1]);
        atomicAdd(&ssq[col], cq[ni][0]);
        atomicAdd(&ssq[col + 1], cq[ni][1]);
    }
    __syncthreads();
    if (tid < 128) {
        atomicAdd(&stat[tid], ssum[tid]);
        atomicAdd(&stat[128 + tid], ssq[tid]);
    }
}

// ---------------------------------------------------------------------------
__global__ void k_bn_finalize(const float* __restrict__ stat,
                              const float* __restrict__ gamma,
                              const float* __restrict__ beta,
                              float* __restrict__ bn) {
    int c = threadIdx.x;
    if (c < 128) {
        float mu  = stat[c] * (1.f / NN);
        float var = stat[128 + c] * (1.f / NN) - mu * mu;
        float sc  = gamma[c] * rsqrtf(var + 1e-5f);
        bn[c]       = sc;
        bn[128 + c] = beta[c] - mu * sc;
    }
}

__global__ void __launch_bounds__(256) k_mlp2(
    const float* __restrict__ H, const float* __restrict__ bn,
    const float* __restrict__ Wm2, float* __restrict__ out) {
    __shared__ float sw[256];
    __shared__ float sb[256];
    int tid = threadIdx.x;
    if (tid < 256) { sw[tid] = Wm2[tid]; sb[tid] = bn[tid]; }
    __syncthreads();
    int g = blockIdx.x * blockDim.x + tid;
    int row = g >> 5, lane = g & 31;
    if (row >= NN) return;
    float4 h = ((const float4*)(H + (long)row * DD))[lane];
    float s0 = 0.f, s1 = 0.f;
    int c = lane * 4;
    float hv[4] = {h.x, h.y, h.z, h.w};
#pragma unroll
    for (int j = 0; j < 4; j++) {
        int cc = c + j;
        float v = fmaxf(hv[j] * sb[cc] + sb[128 + cc], 0.f);
        s0 += v * sw[cc * 2];
        s1 += v * sw[cc * 2 + 1];
    }
#pragma unroll
    for (int off = 16; off > 0; off >>= 1) {
        s0 += __shfl_down_sync(0xffffffffu, s0, off);
        s1 += __shfl_down_sync(0xffffffffu, s1, off);
    }
    if (lane == 0) {
        out[row * 2]     = s0;
        out[row * 2 + 1] = s1;
    }
}

// ---------------------------------------------------------------------------
extern "C" void kernel_launch(void* const* d_in, const int* in_sizes, int n_in,
                              void* d_out, int out_size) {
    const float* xA    = (const float*)d_in[0];
    const float* xB    = (const float*)d_in[1];
    const int*   s0    = (const int*)d_in[2];
    const int*   d0    = (const int*)d_in[3];
    const int*   s1    = (const int*)d_in[4];
    const int*   d1    = (const int*)d_in[5];
    const float* W1r0  = (const float*)d_in[6];
    const float* b1r0  = (const float*)d_in[7];
    const float* W1r1  = (const float*)d_in[8];
    const float* b1r1  = (const float*)d_in[9];
    const float* W2r0  = (const float*)d_in[10];
    const float* b2r0  = (const float*)d_in[11];
    const float* W2r1  = (const float*)d_in[12];
    const float* b2r1  = (const float*)d_in[13];
    const float* Wm1   = (const float*)d_in[14];
    const float* gamma = (const float*)d_in[15];
    const float* beta  = (const float*)d_in[16];
    const float* Wm2   = (const float*)d_in[17];
    float* out = (float*)d_out;

    float* S = nullptr;
    cudaGetSymbolAddress((void**)&S, g_s);
    int* I = nullptr;
    cudaGetSymbolAddress((void**)&I, g_i);

    float* AGG1B = S + OFF_AGG1B;
    float* AGG1A = S + OFF_AGG1A;
    float* AGG2B = S + OFF_AGG2B;
    float* AGG2A = S + OFF_AGG2A;
    float* HB    = S + OFF_HB;
    float* HA    = S + OFF_HA;
    float* H2A   = S + OFF_H2A;
    float* H2B   = S + OFF_H2B;
    float* HMLP  = S + OFF_HMLP;
    float* RS    = S + OFF_RS;
    float* STATS = S + OFF_STATS;
    float* BN    = S + OFF_BN;
    float* WT    = S + OFF_WT;

    int* eidx0 = I + IOFF_EIDX0;
    int* eidx1 = I + IOFF_EIDX1;
    int* od0   = I + IOFF_OD0;
    int* cnt0  = I + IOFF_CNT0;
    int* od1   = I + IOFF_OD1;
    int* cnt1  = I + IOFF_CNT1;
    int* rp0   = I + IOFF_RP0;
    int* rp1   = I + IOFF_RP1;
    int* cur0  = I + IOFF_CUR0;
    int* cur1  = I + IOFF_CUR1;
    int* bsum  = I + IOFF_BSUM;

    float* rs_src0 = RS + 0 * NN;
    float* rs_dst0 = RS + 1 * NN;
    float* rs_src1 = RS + 2 * NN;
    float* rs_dst1 = RS + 3 * NN;

    float* W1r0T = WT + 0;
    float* W1r1T = WT + 32768;
    float* W2r0T = WT + 65536;
    float* W2r1T = WT + 98304;
    float* Wm1T  = WT + 131072;

    cudaFuncSetAttribute(k_gemm_tf32, cudaFuncAttributeMaxDynamicSharedMemorySize, (int)SMEM_T);
    cudaFuncSetAttribute(k_mlp1_tf32, cudaFuncAttributeMaxDynamicSharedMemorySize, (int)SMEM_T);

    // 1) zero degree histograms + STATS
    k_zero<<<(NN + 255) / 256, 256>>>((float*)od0, NN);
    k_zero<<<1, 64>>>(STATS, 64);

    // 2) degree histograms + weight prep
    k_hist<<<(EE + 255) / 256, 256>>>(s0, d0, s1, d1, od0, cnt0, od1, cnt1);
    k_wprep<<<384, 256>>>(W1r0, W1r1, W2r0, W2r1, Wm1, WT);

    // 3) multi-block scan + rs arrays
    {
        dim3 gb(NBLK, 2);
        k_bsum<<<gb, 256>>>(cnt0, cnt1, bsum);
        k_bscan<<<dim3(1, 2), 256>>>(bsum);
        k_rowptr<<<gb, 256>>>(cnt0, cnt1, bsum, rp0, rp1, cur0, cur1);
    }
    k_rs<<<(NN + 255) / 256, 256>>>(od0, cnt0, od1, cnt1, RS);

    // 4) CSR fill
    k_fill<<<(EE + 255) / 256, 256>>>(s0, d0, s1, d1, cur0, eidx0, cur1, eidx1);

    int ggrid = (NN * 32 + 255) / 256;
    int tgrid = (NN + 127) / 128;

    // 5) conv1 gathers
    k_gather<<<ggrid, 256>>>(xA, eidx0, rp0, rs_src0, AGG1B, 1);
    k_gather<<<ggrid, 256>>>(xB, eidx1, rp1, rs_src1, AGG1A, 1);

    // 6) conv1 GEMMs (fold next layer's rs_src into outputs)
    k_gemm_tf32<<<tgrid, 256, SMEM_T>>>(AGG1B, rs_dst0, W1r0T, b1r0, HB, 1, rs_src1);
    k_gemm_tf32<<<tgrid, 256, SMEM_T>>>(AGG1A, rs_dst1, W1r1T, b1r1, HA, 1, rs_src0);

    // 7) conv2 gathers
    k_gather<<<ggrid, 256>>>(HA, eidx0, rp0, nullptr, AGG2B, 0);
    k_gather<<<ggrid, 256>>>(HB, eidx1, rp1, nullptr, AGG2A, 0);

    // 8) conv2 GEMMs
    k_gemm_tf32<<<tgrid, 256, SMEM_T>>>(AGG2B, rs_dst0, W2r0T, b2r0, H2B, 0, nullptr);
    k_gemm_tf32<<<tgrid, 256, SMEM_T>>>(AGG2A, rs_dst1, W2r1T, b2r1, H2A, 0, nullptr);

    // 9) MLP layer 1 + BN stats
    k_mlp1_tf32<<<tgrid, 256, SMEM_T>>>(H2A, H2B, Wm1T, HMLP, STATS);

    // 10) BN finalize + head
    k_bn_finalize<<<1, 128>>>(STATS, gamma, beta, BN);
    k_mlp2<<<(NN * 32 + 255) / 256, 256>>>(HMLP, BN, Wm2, out);
}

// round 6
// speedup vs baseline: 1.5726x; 1.1171x over previous
#include <cuda_runtime.h>
#include <cuda_bf16.h>
#include <math.h>

#define NN 50000
#define EE 600000
#define DD 128
#define NF (NN*DD)
#define NBLK 196   // ceil(NN/256)

// ---------------------------------------------------------------------------
// bf16 helpers
__device__ __forceinline__ unsigned packbf(float even, float odd) {
    unsigned d;
    // d.hi = bf16(%1), d.lo = bf16(%2)
    asm("cvt.rn.bf16x2.f32 %0, %1, %2;" : "=r"(d) : "f"(odd), "f"(even));
    return d;
}
__device__ __forceinline__ float bfres(float v) {   // residual after bf16 rn
    return v - __bfloat162float(__float2bfloat16(v));
}
__device__ __forceinline__ void mma_bf16(
    float& d0, float& d1, float& d2, float& d3,
    unsigned a0, unsigned a1, unsigned a2, unsigned a3,
    unsigned b0, unsigned b1) {
    asm volatile(
        "mma.sync.aligned.m16n8k16.row.col.f32.bf16.bf16.f32 "
        "{%0,%1,%2,%3},{%4,%5,%6,%7},{%8,%9},{%0,%1,%2,%3};"
        : "+f"(d0), "+f"(d1), "+f"(d2), "+f"(d3)
        : "r"(a0), "r"(a1), "r"(a2), "r"(a3), "r"(b0), "r"(b1));
}

// ---------------------------------------------------------------------------
#define OFF_AGG1B 0ULL
#define OFF_AGG1A (1ULL*NF)
#define OFF_AGG2B (2ULL*NF)
#define OFF_AGG2A (3ULL*NF)
#define OFF_HB    (4ULL*NF)
#define OFF_HA    (5ULL*NF)
#define OFF_H2A   (6ULL*NF)
#define OFF_H2B   (7ULL*NF)
#define OFF_HMLP  (8ULL*NF)
#define OFF_RS    (9ULL*NF)
#define OFF_STATS (9ULL*NF + 4ULL*NN)
#define OFF_BN    (OFF_STATS + 256ULL)
#define OFF_WT    (OFF_BN + 256ULL)
#define SCRATCH_FLOATS (OFF_WT + 196608ULL)

__device__ __align__(256) float g_s[SCRATCH_FLOATS];

#define IOFF_EIDX0 0
#define IOFF_EIDX1 (EE)
#define IOFF_OD0   (2*EE)
#define IOFF_CNT0  (2*EE + NN)
#define IOFF_OD1   (2*EE + 2*NN)
#define IOFF_CNT1  (2*EE + 3*NN)
#define IOFF_RP0   (2*EE + 4*NN)
#define IOFF_RP1   (2*EE + 5*NN + 1)
#define IOFF_CUR0  (2*EE + 6*NN + 2)
#define IOFF_CUR1  (2*EE + 7*NN + 2)
#define IOFF_BSUM  (2*EE + 8*NN + 2)
#define SCRATCH_INTS (IOFF_BSUM + 2*NBLK)

__device__ __align__(256) int g_i[SCRATCH_INTS];

// ---------------------------------------------------------------------------
__global__ void k_zero2(int* __restrict__ deg, float* __restrict__ stats) {
    int i = blockIdx.x * 256 + threadIdx.x;
    if (i < NN) ((int4*)deg)[i] = make_int4(0, 0, 0, 0);   // 4*NN ints
    if (i < 64) ((float4*)stats)[i] = make_float4(0.f, 0.f, 0.f, 0.f);
}

__global__ void k_hist(const int* __restrict__ s0, const int* __restrict__ d0,
                       const int* __restrict__ s1, const int* __restrict__ d1,
                       int* __restrict__ od0, int* __restrict__ cnt0,
                       int* __restrict__ od1, int* __restrict__ cnt1) {
    int i = blockIdx.x * blockDim.x + threadIdx.x;
    if (i < EE) {
        atomicAdd(&od0[s0[i]], 1);
        atomicAdd(&cnt0[d0[i]], 1);
        atomicAdd(&od1[s1[i]], 1);
        atomicAdd(&cnt1[d1[i]], 1);
    }
}

__global__ void k_bsum(const int* __restrict__ c0, const int* __restrict__ c1,
                       int* __restrict__ bsum) {
    const int* cnt = blockIdx.y ? c1 : c0;
    int i = blockIdx.x * 256 + threadIdx.x;
    int v = (i < NN) ? cnt[i] : 0;
    __shared__ int sred[8];
#pragma unroll
    for (int off = 16; off; off >>= 1) v += __shfl_down_sync(0xffffffffu, v, off);
    if ((threadIdx.x & 31) == 0) sred[threadIdx.x >> 5] = v;
    __syncthreads();
    if (threadIdx.x < 8) {
        int s = sred[threadIdx.x];
#pragma unroll
        for (int off = 4; off; off >>= 1) s += __shfl_down_sync(0xffu, s, off);
        if (threadIdx.x == 0) bsum[blockIdx.y * NBLK + blockIdx.x] = s;
    }
}

__global__ void k_bscan(int* __restrict__ bsum) {
    __shared__ int sp[256];
    int t = threadIdx.x;
    int* p = bsum + blockIdx.y * NBLK;
    int v = (t < NBLK) ? p[t] : 0;
    sp[t] = v;
    __syncthreads();
#pragma unroll
    for (int off = 1; off < 256; off <<= 1) {
        int u = (t >= off) ? sp[t - off] : 0;
        __syncthreads();
        sp[t] += u;
        __syncthreads();
    }
    if (t < NBLK) p[t] = sp[t] - v;
}

__global__ void k_rowptr(const int* __restrict__ c0, const int* __restrict__ c1,
                         const int* __restrict__ bsum,
                         int* __restrict__ rp0, int* __restrict__ rp1,
                         int* __restrict__ cur0, int* __restrict__ cur1) {
    const int* cnt = blockIdx.y ? c1 : c0;
    int* rp  = blockIdx.y ? rp1 : rp0;
    int* cur = blockIdx.y ? cur1 : cur0;
    __shared__ int sp[256];
    int t = threadIdx.x;
    int i = blockIdx.x * 256 + t;
    int v = (i < NN) ? cnt[i] : 0;
    sp[t] = v;
    __syncthreads();
#pragma unroll
    for (int off = 1; off < 256; off <<= 1) {
        int u = (t >= off) ? sp[t - off] : 0;
        __syncthreads();
        sp[t] += u;
        __syncthreads();
    }
    if (i < NN) {
        int ex = sp[t] - v + bsum[blockIdx.y * NBLK + blockIdx.x];
        rp[i] = ex;
        cur[i] = ex;
    }
    if (i == NN - 1) rp[NN] = EE;
}

__global__ void k_rs(const int* __restrict__ od0, const int* __restrict__ cnt0,
                     const int* __restrict__ od1, const int* __restrict__ cnt1,
                     float* __restrict__ rs) {
    int i = blockIdx.x * blockDim.x + threadIdx.x;
    if (i < NN) {
        rs[0 * NN + i] = rsqrtf((float)max(od0[i], 1));
        rs[1 * NN + i] = rsqrtf((float)max(cnt0[i], 1));
        rs[2 * NN + i] = rsqrtf((float)max(od1[i], 1));
        rs[3 * NN + i] = rsqrtf((float)max(cnt1[i], 1));
    }
}

__global__ void k_fill(const int* __restrict__ s0, const int* __restrict__ d0,
                       const int* __restrict__ s1, const int* __restrict__ d1,
                       int* __restrict__ cur0, int* __restrict__ eidx0,
                       int* __restrict__ cur1, int* __restrict__ eidx1) {
    int i = blockIdx.x * blockDim.x + threadIdx.x;
    if (i < EE) {
        int p0 = atomicAdd(&cur0[d0[i]], 1);
        eidx0[p0] = s0[i];
        int p1 = atomicAdd(&cur1[d1[i]], 1);
        eidx1[p1] = s1[i];
    }
}

// ---------------------------------------------------------------------------
// weight prep: transpose + bf16 hi/lo split, packed bf16x2 along k.
// conv mat m (0..3): hi plane at WT[m*16384 + n*64 + ku], lo at +8192  (u32)
// Wm1: hi at WT[65536 + n*128 + ku], lo at +16384
__global__ void k_wprep(const float* __restrict__ W1r0, const float* __restrict__ W1r1,
                        const float* __restrict__ W2r0, const float* __restrict__ W2r1,
                        const float* __restrict__ Wm1, unsigned* __restrict__ WT) {
    int idx = blockIdx.x * 256 + threadIdx.x;
    if (idx < 32768) {
        int mat = idx >> 13, r = idx & 8191;
        int n = r >> 6, ku = r & 63;
        int k = 2 * ku;
        const float* Wsrc = (mat == 0) ? W1r0 : (mat == 1) ? W1r1 :
                            (mat == 2) ? W2r0 : W2r1;
        float v0 = __ldg(Wsrc + k * 128 + n);
        float v1 = __ldg(Wsrc + (k + 1) * 128 + n);
        WT[mat * 16384 + n * 64 + ku]        = packbf(v0, v1);
        WT[mat * 16384 + 8192 + n * 64 + ku] = packbf(bfres(v0), bfres(v1));
    } else if (idx < 49152) {
        int r = idx - 32768;
        int n = r >> 7, ku = r & 127;
        int k = 2 * ku;
        float v0 = __ldg(Wm1 + k * 128 + n);
        float v1 = __ldg(Wm1 + (k + 1) * 128 + n);
        WT[65536 + n * 128 + ku]         = packbf(v0, v1);
        WT[65536 + 16384 + n * 128 + ku] = packbf(bfres(v0), bfres(v1));
    }
}

// ---------------------------------------------------------------------------
// merged gather over both relations (blockIdx.y selects relation)
__global__ void __launch_bounds__(256) k_gather2(
    const float* __restrict__ xa, const int* __restrict__ ea,
    const int* __restrict__ rpa, const float* __restrict__ rsa,
    float* __restrict__ agga,
    const float* __restrict__ xb, const int* __restrict__ eb,
    const int* __restrict__ rpb, const float* __restrict__ rsb,
    float* __restrict__ aggb, int useRs) {
    const float* x  = blockIdx.y ? xb : xa;
    const int* eidx = blockIdx.y ? eb : ea;
    const int* rowptr = blockIdx.y ? rpb : rpa;
    const float* rs_src = blockIdx.y ? rsb : rsa;
    float* agg = blockIdx.y ? aggb : agga;

    int g = blockIdx.x * blockDim.x + threadIdx.x;
    int r = g >> 5, lane = g & 31;
    if (r >= NN) return;
    int beg = __ldg(rowptr + r), end = __ldg(rowptr + r + 1);
    float4 acc = make_float4(0.f, 0.f, 0.f, 0.f);
    float4 acc2 = make_float4(0.f, 0.f, 0.f, 0.f);
    int e = beg;
    if (useRs) {
        for (; e + 1 < end; e += 2) {
            int sa = __ldg(eidx + e), sb = __ldg(eidx + e + 1);
            float ra = __ldg(rs_src + sa), rb = __ldg(rs_src + sb);
            float4 va = __ldg((const float4*)(x + (long)sa * DD) + lane);
            float4 vb = __ldg((const float4*)(x + (long)sb * DD) + lane);
            acc.x += va.x * ra; acc.y += va.y * ra;
            acc.z += va.z * ra; acc.w += va.w * ra;
            acc2.x += vb.x * rb; acc2.y += vb.y * rb;
            acc2.z += vb.z * rb; acc2.w += vb.w * rb;
        }
        if (e < end) {
            int sa = __ldg(eidx + e);
            float ra = __ldg(rs_src + sa);
            float4 va = __ldg((const float4*)(x + (long)sa * DD) + lane);
            acc.x += va.x * ra; acc.y += va.y * ra;
            acc.z += va.z * ra; acc.w += va.w * ra;
        }
    } else {
        for (; e + 1 < end; e += 2) {
            int sa = __ldg(eidx + e), sb = __ldg(eidx + e + 1);
            float4 va = __ldg((const float4*)(x + (long)sa * DD) + lane);
            float4 vb = __ldg((const float4*)(x + (long)sb * DD) + lane);
            acc.x += va.x; acc.y += va.y; acc.z += va.z; acc.w += va.w;
            acc2.x += vb.x; acc2.y += vb.y; acc2.z += vb.z; acc2.w += vb.w;
        }
        if (e < end) {
            int sa = __ldg(eidx + e);
            float4 va = __ldg((const float4*)(x + (long)sa * DD) + lane);
            acc.x += va.x; acc.y += va.y; acc.z += va.z; acc.w += va.w;
        }
    }
    acc.x += acc2.x; acc.y += acc2.y; acc.z += acc2.z; acc.w += acc2.w;
    ((float4*)(agg + (long)r * DD))[lane] = acc;
}

// ---------------------------------------------------------------------------
// bf16x3 tensor-core GEMM, 64-row tiles, both relations per launch (grid.y=2).
// smem (u32): A_hi[64][68], A_lo[64][68], W_hi[128][68], W_lo[128][68]
#define U_AHI 0
#define U_ALO 4352
#define U_WHI 8704
#define U_WLO 17408
#define SMEM_G ((size_t)26112 * 4)   // 104448 B

__global__ void __launch_bounds__(256, 2) k_gemm_bf16(
    const float* __restrict__ X0, const float* __restrict__ rsi0,
    const unsigned* __restrict__ Wp0, const float* __restrict__ bp0,
    float* __restrict__ out0, const float* __restrict__ rso0,
    const float* __restrict__ X1, const float* __restrict__ rsi1,
    const unsigned* __restrict__ Wp1, const float* __restrict__ bp1,
    float* __restrict__ out1, const float* __restrict__ rso1,
    int doRelu) {
    extern __shared__ unsigned smu[];
    unsigned* sAhi = smu + U_AHI;
    unsigned* sAlo = smu + U_ALO;
    unsigned* sWhi = smu + U_WHI;
    unsigned* sWlo = smu + U_WLO;

    const float* X = blockIdx.y ? X1 : X0;
    const float* rsi = blockIdx.y ? rsi1 : rsi0;
    const unsigned* Wp = blockIdx.y ? Wp1 : Wp0;
    const float* bp = blockIdx.y ? bp1 : bp0;
    float* out = blockIdx.y ? out1 : out0;
    const float* rso = blockIdx.y ? rso1 : rso0;

    int tid = threadIdx.x;
    int r0 = blockIdx.x * 64;

    // stage A: 64 rows x 32 float4 (FULL 128 floats per row)
    for (int i = tid; i < 2048; i += 256) {
        int row = i >> 5, f4 = i & 31;
        int gr = r0 + row;
        float4 v = make_float4(0.f, 0.f, 0.f, 0.f);
        if (gr < NN) {
            v = __ldg((const float4*)(X + (long)gr * DD) + f4);
            float r = __ldg(rsi + gr);
            v.x *= r; v.y *= r; v.z *= r; v.w *= r;
        }
        ((uint2*)(sAhi + row * 68))[f4] = make_uint2(packbf(v.x, v.y), packbf(v.z, v.w));
        ((uint2*)(sAlo + row * 68))[f4] = make_uint2(
            packbf(bfres(v.x), bfres(v.y)), packbf(bfres(v.z), bfres(v.w)));
    }
    // stage W: 128 cols x 32 uint2 per plane (64 words = 128 k)
    for (int i = tid; i < 4096; i += 256) {
        int n = i >> 5, q = i & 31;
        ((uint2*)(sWhi + n * 68))[q] = __ldg((const uint2*)(Wp + n * 64) + q);
        ((uint2*)(sWlo + n * 68))[q] = __ldg((const uint2*)(Wp + 8192 + n * 64) + q);
    }
    __syncthreads();

    int lane = tid & 31, w = tid >> 5;
    int mg = w >> 2, ng = w & 3;       // mg 0..1 (32 rows each), ng 0..3 (32 cols)
    int tg = lane & 3, gid = lane >> 2;

    float acc[2][4][4];
#pragma unroll
    for (int mi = 0; mi < 2; mi++)
#pragma unroll
        for (int ni = 0; ni < 4; ni++)
#pragma unroll
            for (int q = 0; q < 4; q++) acc[mi][ni][q] = 0.f;

#pragma unroll
    for (int ks = 0; ks < 8; ks++) {
        unsigned Ah[2][4], Al[2][4], Bh[4][2], Bl[4][2];
#pragma unroll
        for (int mi = 0; mi < 2; mi++) {
            int base = (mg * 32 + mi * 16 + gid) * 68 + ks * 8 + tg;
            Ah[mi][0] = sAhi[base];
            Ah[mi][1] = sAhi[base + 8 * 68];
            Ah[mi][2] = sAhi[base + 4];
            Ah[mi][3] = sAhi[base + 8 * 68 + 4];
            Al[mi][0] = sAlo[base];
            Al[mi][1] = sAlo[base + 8 * 68];
            Al[mi][2] = sAlo[base + 4];
            Al[mi][3] = sAlo[base + 8 * 68 + 4];
        }
#pragma unroll
        for (int ni = 0; ni < 4; ni++) {
            int cb = (ng * 32 + ni * 8 + gid) * 68 + ks * 8 + tg;
            Bh[ni][0] = sWhi[cb];
            Bh[ni][1] = sWhi[cb + 4];
            Bl[ni][0] = sWlo[cb];
            Bl[ni][1] = sWlo[cb + 4];
        }
#pragma unroll
        for (int mi = 0; mi < 2; mi++)
#pragma unroll
            for (int ni = 0; ni < 4; ni++) {
                float* d = acc[mi][ni];
                mma_bf16(d[0], d[1], d[2], d[3],
                         Ah[mi][0], Ah[mi][1], Ah[mi][2], Ah[mi][3],
                         Bh[ni][0], Bh[ni][1]);
                mma_bf16(d[0], d[1], d[2], d[3],
                         Ah[mi][0], Ah[mi][1], Ah[mi][2], Ah[mi][3],
                         Bl[ni][0], Bl[ni][1]);
                mma_bf16(d[0], d[1], d[2], d[3],
                         Al[mi][0], Al[mi][1], Al[mi][2], Al[mi][3],
                         Bh[ni][0], Bh[ni][1]);
            }
    }

#pragma unroll
    for (int ni = 0; ni < 4; ni++) {
        int col = ng * 32 + ni * 8 + 2 * tg;
        float bb0 = __ldg(bp + col), bb1 = __ldg(bp + col + 1);
#pragma unroll
        for (int mi = 0; mi < 2; mi++) {
            int gr = r0 + mg * 32 + mi * 16 + gid;
            if (gr < NN) {
                float ro = rso ? __ldg(rso + gr) : 1.f;
                float v0 = acc[mi][ni][0] + bb0;
                float v1 = acc[mi][ni][1] + bb1;
                if (doRelu) { v0 = fmaxf(v0, 0.f); v1 = fmaxf(v1, 0.f); }
                *(float2*)(out + (long)gr * DD + col) = make_float2(v0 * ro, v1 * ro);
            }
            int gr8 = gr + 8;
            if (gr8 < NN) {
                float ro = rso ? __ldg(rso + gr8) : 1.f;
                float v2 = acc[mi][ni][2] + bb0;
                float v3 = acc[mi][ni][3] + bb1;
                if (doRelu) { v2 = fmaxf(v2, 0.f); v3 = fmaxf(v3, 0.f); }
                *(float2*)(out + (long)gr8 * DD + col) = make_float2(v2 * ro, v3 * ro);
            }
        }
    }
}

// ---------------------------------------------------------------------------
// MLP layer1 (implicit concat), bf16x3, K=256 via 2 phases; + BN stats
__global__ void __launch_bounds__(256, 2) k_mlp1_bf16(
    const float* __restrict__ XA, const float* __restrict__ XB,
    const unsigned* __restrict__ WTm1, float* __restrict__ out,
    float* __restrict__ stat) {
    extern __shared__ unsigned smu[];
    unsigned* sAhi = smu + U_AHI;
    unsigned* sAlo = smu + U_ALO;
    unsigned* sWhi = smu + U_WHI;
    unsigned* sWlo = smu + U_WLO;
    int tid = threadIdx.x;
    int r0 = blockIdx.x * 64;
    int lane = tid & 31, w = tid >> 5;
    int mg = w >> 2, ng = w & 3;
    int tg = lane & 3, gid = lane >> 2;

    float acc[2][4][4];
#pragma unroll
    for (int mi = 0; mi < 2; mi++)
#pragma unroll
        for (int ni = 0; ni < 4; ni++)
#pragma unroll
            for (int q = 0; q < 4; q++) acc[mi][ni][q] = 0.f;

    for (int ph = 0; ph < 2; ph++) {
        const float* X = ph ? XB : XA;
        // stage A: FULL 128 floats per row
        for (int i = tid; i < 2048; i += 256) {
            int row = i >> 5, f4 = i & 31;
            int gr = r0 + row;
            float4 v = make_float4(0.f, 0.f, 0.f, 0.f);
            if (gr < NN) v = __ldg((const float4*)(X + (long)gr * DD) + f4);
            ((uint2*)(sAhi + row * 68))[f4] = make_uint2(packbf(v.x, v.y), packbf(v.z, v.w));
            ((uint2*)(sAlo + row * 68))[f4] = make_uint2(
                packbf(bfres(v.x), bfres(v.y)), packbf(bfres(v.z), bfres(v.w)));
        }
        for (int i = tid; i < 4096; i += 256) {
            int n = i >> 5, q = i & 31;
            ((uint2*)(sWhi + n * 68))[q] =
                __ldg((const uint2*)(WTm1 + n * 128 + ph * 64) + q);
            ((uint2*)(sWlo + n * 68))[q] =
                __ldg((const uint2*)(WTm1 + 16384 + n * 128 + ph * 64) + q);
        }
        __syncthreads();

#pragma unroll
        for (int ks = 0; ks < 8; ks++) {
            unsigned Ah[2][4], Al[2][4], Bh[4][2], Bl[4][2];
#pragma unroll
            for (int mi = 0; mi < 2; mi++) {
                int base = (mg * 32 + mi * 16 + gid) * 68 + ks * 8 + tg;
                Ah[mi][0] = sAhi[base];
                Ah[mi][1] = sAhi[base + 8 * 68];
                Ah[mi][2] = sAhi[base + 4];
                Ah[mi][3] = sAhi[base + 8 * 68 + 4];
                Al[mi][0] = sAlo[base];
                Al[mi][1] = sAlo[base + 8 * 68];
                Al[mi][2] = sAlo[base + 4];
                Al[mi][3] = sAlo[base + 8 * 68 + 4];
            }
#pragma unroll
            for (int ni = 0; ni < 4; ni++) {
                int cb = (ng * 32 + ni * 8 + gid) * 68 + ks * 8 + tg;
                Bh[ni][0] = sWhi[cb];
                Bh[ni][1] = sWhi[cb + 4];
                Bl[ni][0] = sWlo[cb];
                Bl[ni][1] = sWlo[cb + 4];
            }
#pragma unroll
            for (int mi = 0; mi < 2; mi++)
#pragma unroll
                for (int ni = 0; ni < 4; ni++) {
                    float* d = acc[mi][ni];
                    mma_bf16(d[0], d[1], d[2], d[3],
                             Ah[mi][0], Ah[mi][1], Ah[mi][2], Ah[mi][3],
                             Bh[ni][0], Bh[ni][1]);
                    mma_bf16(d[0], d[1], d[2], d[3],
                             Ah[mi][0], Ah[mi][1], Ah[mi][2], Ah[mi][3],
                             Bl[ni][0], Bl[ni][1]);
                    mma_bf16(d[0], d[1], d[2], d[3],
                             Al[mi][0], Al[mi][1], Al[mi][2], Al[mi][3],
                             Bh[ni][0], Bh[ni][1]);
                }
        }
        __syncthreads();
    }

    // epilogue + BN stats
    float cs[4][2], cq[4][2];
#pragma unroll
    for (int ni = 0; ni < 4; ni++) {
        cs[ni][0] = cs[ni][1] = 0.f;
        cq[ni][0] = cq[ni][1] = 0.f;
    }
#pragma unroll
    for (int ni = 0; ni < 4; ni++) {
        int col = ng * 32 + ni * 8 + 2 * tg;
#pragma unroll
        for (int mi = 0; mi < 2; mi++) {
            int gr = r0 + mg * 32 + mi * 16 + gid;
            if (gr < NN) {
                float v0 = acc[mi][ni][0], v1 = acc[mi][ni][1];
                *(float2*)(out + (long)gr * DD + col) = make_float2(v0, v1);
                cs[ni][0] += v0; cq[ni][0] += v0 * v0;
                cs[ni][1] += v1; cq[ni][1] += v1 * v1;
            }
            int gr8 = gr + 8;
            if (gr8 < NN) {
                float v2 = acc[mi][ni][2], v3 = acc[mi][ni][3];
                *(float2*)(out + (long)gr8 * DD + col) = make_float2(v2, v3);
                cs[ni][0] += v2; cq[ni][0] += v2 * v2;
                cs[ni][1] += v3; cq[ni][1] += v3 * v3;
            }
        }
    }
    __syncthreads();
    float* ssum = (float*)smu;
    float* ssq  = (float*)smu + 128;
    if (tid < 256) ((float*)smu)[tid] = 0.f;
    __syncthreads();
#pragma unroll
    for (int ni = 0; ni < 4; ni++) {
        int col = ng * 32 + ni * 8 + 2 * tg;
        atomicAdd(&ssum[col], cs[ni][0]);
        atomicAdd(&ssum[col + 1], cs[ni][1]);
        atomicAdd(&ssq[col], cq[ni][0]);
        atomicAdd(&ssq[col + 1], cq[ni][1]);
    }
    __syncthreads();
    if (tid < 128) {
        atomicAdd(&stat[tid], ssum[tid]);
        atomicAdd(&stat[128 + tid], ssq[tid]);
    }
}

// ---------------------------------------------------------------------------
__global__ void k_bn_finalize(const float* __restrict__ stat,
                              const float* __restrict__ gamma,
                              const float* __restrict__ beta,
                              float* __restrict__ bn) {
    int c = threadIdx.x;
    if (c < 128) {
        float mu  = stat[c] * (1.f / NN);
        float var = stat[128 + c] * (1.f / NN) - mu * mu;
        float sc  = gamma[c] * rsqrtf(var + 1e-5f);
        bn[c]       = sc;
        bn[128 + c] = beta[c] - mu * sc;
    }
}

__global__ void __launch_bounds__(256) k_mlp2(
    const float* __restrict__ H, const float* __restrict__ bn,
    const float* __restrict__ Wm2, float* __restrict__ out) {
    __shared__ float sw[256];
    __shared__ float sb[256];
    int tid = threadIdx.x;
    if (tid < 256) { sw[tid] = Wm2[tid]; sb[tid] = bn[tid]; }
    __syncthreads();
    int g = blockIdx.x * blockDim.x + tid;
    int row = g >> 5, lane = g & 31;
    if (row >= NN) return;
    float4 h = ((const float4*)(H + (long)row * DD))[lane];
    float s0 = 0.f, s1 = 0.f;
    int c = lane * 4;
    float hv[4] = {h.x, h.y, h.z, h.w};
#pragma unroll
    for (int j = 0; j < 4; j++) {
        int cc = c + j;
        float v = fmaxf(hv[j] * sb[cc] + sb[128 + cc], 0.f);
        s0 += v * sw[cc * 2];
        s1 += v * sw[cc * 2 + 1];
    }
#pragma unroll
    for (int off = 16; off > 0; off >>= 1) {
        s0 += __shfl_down_sync(0xffffffffu, s0, off);
        s1 += __shfl_down_sync(0xffffffffu, s1, off);
    }
    if (lane == 0) {
        out[row * 2]     = s0;
        out[row * 2 + 1] = s1;
    }
}

// ---------------------------------------------------------------------------
extern "C" void kernel_launch(void* const* d_in, const int* in_sizes, int n_in,
                              void* d_out, int out_size) {
    const float* xA    = (const float*)d_in[0];
    const float* xB    = (const float*)d_in[1];
    const int*   s0    = (const int*)d_in[2];
    const int*   d0    = (const int*)d_in[3];
    const int*   s1    = (const int*)d_in[4];
    const int*   d1    = (const int*)d_in[5];
    const float* W1r0  = (const float*)d_in[6];
    const float* b1r0  = (const float*)d_in[7];
    const float* W1r1  = (const float*)d_in[8];
    const float* b1r1  = (const float*)d_in[9];
    const float* W2r0  = (const float*)d_in[10];
    const float* b2r0  = (const float*)d_in[11];
    const float* W2r1  = (const float*)d_in[12];
    const float* b2r1  = (const float*)d_in[13];
    const float* Wm1   = (const float*)d_in[14];
    const float* gamma = (const float*)d_in[15];
    const float* beta  = (const float*)d_in[16];
    const float* Wm2   = (const float*)d_in[17];
    float* out = (float*)d_out;

    float* S = nullptr;
    cudaGetSymbolAddress((void**)&S, g_s);
    int* I = nullptr;
    cudaGetSymbolAddress((void**)&I, g_i);

    float* AGG1B = S + OFF_AGG1B;
    float* AGG1A = S + OFF_AGG1A;
    float* AGG2B = S + OFF_AGG2B;
    float* AGG2A = S + OFF_AGG2A;
    float* HB    = S + OFF_HB;
    float* HA    = S + OFF_HA;
    float* H2A   = S + OFF_H2A;
    float* H2B   = S + OFF_H2B;
    float* HMLP  = S + OFF_HMLP;
    float* RS    = S + OFF_RS;
    float* STATS = S + OFF_STATS;
    float* BN    = S + OFF_BN;
    unsigned* WT = (unsigned*)(S + OFF_WT);

    int* eidx0 = I + IOFF_EIDX0;
    int* eidx1 = I + IOFF_EIDX1;
    int* od0   = I + IOFF_OD0;
    int* cnt0  = I + IOFF_CNT0;
    int* od1   = I + IOFF_OD1;
    int* cnt1  = I + IOFF_CNT1;
    int* rp0   = I + IOFF_RP0;
    int* rp1   = I + IOFF_RP1;
    int* cur0  = I + IOFF_CUR0;
    int* cur1  = I + IOFF_CUR1;
    int* bsum  = I + IOFF_BSUM;

    float* rs_src0 = RS + 0 * NN;
    float* rs_dst0 = RS + 1 * NN;
    float* rs_src1 = RS + 2 * NN;
    float* rs_dst1 = RS + 3 * NN;

    unsigned* W1r0T = WT + 0;
    unsigned* W1r1T = WT + 16384;
    unsigned* W2r0T = WT + 32768;
    unsigned* W2r1T = WT + 49152;
    unsigned* Wm1T  = WT + 65536;

    cudaFuncSetAttribute(k_gemm_bf16, cudaFuncAttributeMaxDynamicSharedMemorySize, (int)SMEM_G);
    cudaFuncSetAttribute(k_mlp1_bf16, cudaFuncAttributeMaxDynamicSharedMemorySize, (int)SMEM_G);

    // 1) zero deg histograms + STATS (fused)
    k_zero2<<<(NN + 255) / 256, 256>>>(od0, STATS);

    // 2) degree histograms + weight prep
    k_hist<<<(EE + 255) / 256, 256>>>(s0, d0, s1, d1, od0, cnt0, od1, cnt1);
    k_wprep<<<192, 256>>>(W1r0, W1r1, W2r0, W2r1, Wm1, WT);

    // 3) multi-block scan + rs arrays
    {
        dim3 gb(NBLK, 2);
        k_bsum<<<gb, 256>>>(cnt0, cnt1, bsum);
        k_bscan<<<dim3(1, 2), 256>>>(bsum);
        k_rowptr<<<gb, 256>>>(cnt0, cnt1, bsum, rp0, rp1, cur0, cur1);
    }
    k_rs<<<(NN + 255) / 256, 256>>>(od0, cnt0, od1, cnt1, RS);

    // 4) CSR fill
    k_fill<<<(EE + 255) / 256, 256>>>(s0, d0, s1, d1, cur0, eidx0, cur1, eidx1);

    dim3 ggrid((NN * 32 + 255) / 256, 2);
    dim3 tgrid((NN + 63) / 64, 2);
    int mgrid = (NN + 63) / 64;

    // 5) conv1 gathers (both relations)
    k_gather2<<<ggrid, 256>>>(xA, eidx0, rp0, rs_src0, AGG1B,
                              xB, eidx1, rp1, rs_src1, AGG1A, 1);

    // 6) conv1 GEMMs (both; fold next layer's rs_src into outputs)
    k_gemm_bf16<<<tgrid, 256, SMEM_G>>>(
        AGG1B, rs_dst0, W1r0T, b1r0, HB, rs_src1,
        AGG1A, rs_dst1, W1r1T, b1r1, HA, rs_src0, 1);

    // 7) conv2 gathers (both)
    k_gather2<<<ggrid, 256>>>(HA, eidx0, rp0, nullptr, AGG2B,
                              HB, eidx1, rp1, nullptr, AGG2A, 0);

    // 8) conv2 GEMMs (both)
    k_gemm_bf16<<<tgrid, 256, SMEM_G>>>(
        AGG2B, rs_dst0, W2r0T, b2r0, H2B, nullptr,
        AGG2A, rs_dst1, W2r1T, b2r1, H2A, nullptr, 0);

    // 9) MLP layer 1 + BN stats
    k_mlp1_bf16<<<mgrid, 256, SMEM_G>>>(H2A, H2B, Wm1T, HMLP, STATS);

    // 10) BN finalize + head
    k_bn_finalize<<<1, 128>>>(STATS, gamma, beta, BN);
    k_mlp2<<<(NN * 32 + 255) / 256, 256>>>(HMLP, BN, Wm2, out);
}